// round 1
// baseline (speedup 1.0000x reference)
#include <cuda_runtime.h>

#define NN 100000          // total nodes
#define NA 50000           // typeA nodes
#define DD 128             // hidden dim
#define KIN 256            // typeA input dim
#define NE 600000          // edges
#define LN_EPS 1e-5f

// ---------------- scratch (device globals: allocation-free) ----------------
__device__ __align__(16) float g_x[(size_t)NN * DD];     // layer-0 input features
__device__ __align__(16) float g_y[(size_t)NN * DD];     // layer-0 output / layer-1 input
__device__ __align__(16) float g_uout[(size_t)NN * DD];  // pre-aggregated out-direction
__device__ __align__(16) float g_uin[(size_t)NN * DD];   // pre-aggregated in-direction
__device__ float g_degs[NN];
__device__ float g_degt[NN];
__device__ float g_invs[NN];
__device__ float g_invt[NN];

// ---------------- small helpers ----------------
__device__ __forceinline__ float4 f4_scale(float4 a, float s) {
    return make_float4(a.x * s, a.y * s, a.z * s, a.w * s);
}
__device__ __forceinline__ float4 f4_sub(float4 a, float4 b) {
    return make_float4(a.x - b.x, a.y - b.y, a.z - b.z, a.w - b.w);
}

// vectorized fp32 reduction to global (sm_90+)
__device__ __forceinline__ void red4(float* p, float4 v) {
    asm volatile("red.global.add.v4.f32 [%0], {%1, %2, %3, %4};"
                 :: "l"(p), "f"(v.x), "f"(v.y), "f"(v.z), "f"(v.w)
                 : "memory");
}

// ---------------- utility kernels ----------------
__global__ void k_zero_u() {
    int n = NN * DD / 4;
    float4* a = (float4*)g_uout;
    float4* b = (float4*)g_uin;
    float4 z = make_float4(0.f, 0.f, 0.f, 0.f);
    for (int i = blockIdx.x * blockDim.x + threadIdx.x; i < n;
         i += gridDim.x * blockDim.x) {
        a[i] = z;
        b[i] = z;
    }
}

__global__ void k_zero_deg() {
    int i = blockIdx.x * blockDim.x + threadIdx.x;
    if (i < NN) { g_degs[i] = 0.f; g_degt[i] = 0.f; }
}

__global__ void k_degree(const int* __restrict__ s, const int* __restrict__ t) {
    int e = blockIdx.x * blockDim.x + threadIdx.x;
    if (e < NE) {
        atomicAdd(&g_degs[s[e]], 1.f);
        atomicAdd(&g_degt[t[e]], 1.f);
    }
}

__global__ void k_inv() {
    int i = blockIdx.x * blockDim.x + threadIdx.x;
    if (i < NN) {
        float ds = g_degs[i];
        float dt = g_degt[i];
        g_invs[i] = ds > 0.f ? rsqrtf(ds) : 0.f;
        g_invt[i] = dt > 0.f ? rsqrtf(dt) : 0.f;
    }
}

__global__ void k_copyB(const float* __restrict__ embB) {
    int n = NA * DD / 4;
    float4* dst = (float4*)(g_x + (size_t)NA * DD);
    const float4* src = (const float4*)embB;
    for (int i = blockIdx.x * blockDim.x + threadIdx.x; i < n;
         i += gridDim.x * blockDim.x) {
        dst[i] = src[i];
    }
}

// ---------------- typeA encoder MLP: g_x[0:NA] = X @ W^T + b ----------------
// 64-row tile, 512 threads, W^T in XOR-swizzled shared memory.
__global__ void __launch_bounds__(512) k_mlp(const float* __restrict__ X,
                                             const float* __restrict__ W,
                                             const float* __restrict__ b) {
    extern __shared__ float sm[];
    float* sw = sm;                 // KIN*DD swizzled transpose of W
    float* su = sm + KIN * DD;      // 64*KIN input tile

    int tid = threadIdx.x;

    // load W[o][k] -> sw at "Wt[k][o]" with float4-level XOR swizzle
    for (int idx = tid; idx < DD * KIN; idx += 512) {
        int o = idx >> 8;           // /KIN
        int k = idx & 255;
        int j = o >> 2, sub = o & 3;
        sw[k * DD + (((j ^ (k & 31)) << 2) + sub)] = W[idx];
    }

    int row0 = blockIdx.x * 64;
    for (int idx = tid; idx < 64 * KIN / 4; idx += 512) {
        int r = idx >> 6;           // KIN/4 = 64 float4 per row
        int c4 = idx & 63;
        int row = row0 + r;
        float4 v = make_float4(0.f, 0.f, 0.f, 0.f);
        if (row < NA) v = ((const float4*)X)[(size_t)row * 64 + c4];
        ((float4*)su)[idx] = v;
    }
    __syncthreads();

    int tx = tid & 31, ty = tid >> 5;
    int c0 = tx * 4, r0 = ty * 4;
    float acc[4][4] = {};
    const float4* sw4 = (const float4*)sw;

    for (int k = 0; k < KIN; k += 4) {
        float4 w0 = sw4[(k + 0) * 32 + (tx ^ ((k + 0) & 31))];
        float4 w1 = sw4[(k + 1) * 32 + (tx ^ ((k + 1) & 31))];
        float4 w2 = sw4[(k + 2) * 32 + (tx ^ ((k + 2) & 31))];
        float4 w3 = sw4[(k + 3) * 32 + (tx ^ ((k + 3) & 31))];
#pragma unroll
        for (int i = 0; i < 4; i++) {
            float4 u = *(const float4*)&su[(r0 + i) * KIN + k];
            acc[i][0] += u.x * w0.x + u.y * w1.x + u.z * w2.x + u.w * w3.x;
            acc[i][1] += u.x * w0.y + u.y * w1.y + u.z * w2.y + u.w * w3.y;
            acc[i][2] += u.x * w0.z + u.y * w1.z + u.z * w2.z + u.w * w3.z;
            acc[i][3] += u.x * w0.w + u.y * w1.w + u.z * w2.w + u.w * w3.w;
        }
    }

    float4 bb = __ldg((const float4*)b + tx);
#pragma unroll
    for (int i = 0; i < 4; i++) {
        int row = row0 + r0 + i;
        if (row < NA) {
            float4 o = make_float4(acc[i][0] + bb.x, acc[i][1] + bb.y,
                                   acc[i][2] + bb.z, acc[i][3] + bb.w);
            *(float4*)&g_x[(size_t)row * DD + c0] = o;
        }
    }
}

// ---------------- edge scatter: one warp per edge ----------------
// u_out[t] += inv_s[s]*(x[s]-rel[r]);  u_in[s] += inv_t[t]*(x[t]-rel[r])
__global__ void k_scatter(int layer, const float* __restrict__ rel,
                          const int* __restrict__ es, const int* __restrict__ er,
                          const int* __restrict__ et) {
    int w = (blockIdx.x * blockDim.x + threadIdx.x) >> 5;
    int lane = threadIdx.x & 31;
    if (w >= NE) return;
    const float* x = layer ? g_y : g_x;

    int si = __ldg(es + w);
    int ri = __ldg(er + w);
    int ti = __ldg(et + w);
    float ws = __ldg(&g_invs[si]);
    float wt = __ldg(&g_invt[ti]);

    float4 a = __ldg((const float4*)(x + (size_t)si * DD) + lane);
    float4 bt = __ldg((const float4*)(x + (size_t)ti * DD) + lane);
    float4 c = __ldg((const float4*)(rel + (size_t)ri * DD) + lane);

    float4 mo = f4_scale(f4_sub(a, c), ws);
    float4 mi = f4_scale(f4_sub(bt, c), wt);

    red4(&g_uout[(size_t)ti * DD + lane * 4], mo);
    red4(&g_uin[(size_t)si * DD + lane * 4], mi);
}

// ---------------- fused conv: 3 matmuls + bias + (relu) + LayerNorm ----------
// y[i] = LN( relu?( (uout[i]*invt[i] + uin[i]*invs[i] + (x[i]-loop)) @ W^T /3 + bias ) )
// (distributed over the three weight matrices)
__global__ void __launch_bounds__(512) k_fused(
    int layer, const float* __restrict__ Wout, const float* __restrict__ Win,
    const float* __restrict__ Wloop, const float* __restrict__ loop_rel,
    const float* __restrict__ bias, const float* __restrict__ lng,
    const float* __restrict__ lnb, float* __restrict__ dout) {
    extern __shared__ float sm[];
    float* sw = sm;                  // 3 * DD*DD swizzled weights
    float* su = sm + 3 * DD * DD;    // 64 * DD input tile

    int tid = threadIdx.x;
    const float* Ws[3] = {Wout, Win, Wloop};
    for (int m = 0; m < 3; m++) {
        const float* W = Ws[m];
        float* swm = sw + m * DD * DD;
        for (int idx = tid; idx < DD * DD; idx += 512) {
            int o = idx >> 7, k = idx & 127;
            int j = o >> 2, sub = o & 3;
            swm[k * DD + (((j ^ (k & 31)) << 2) + sub)] = W[idx];
        }
    }

    int row0 = blockIdx.x * 64;
    int tx = tid & 31, ty = tid >> 5;
    int c0 = tx * 4, r0 = ty * 4;
    const float* x = layer ? g_y : g_x;
    float* out = layer ? dout : g_y;

    float acc[4][4] = {};

    for (int m = 0; m < 3; m++) {
        __syncthreads();
        // load (scaled) input tile: 64 rows x 128 cols = 2048 float4
        for (int idx = tid; idx < 64 * DD / 4; idx += 512) {
            int r = idx >> 5;       // DD/4 = 32 float4 per row
            int c4 = idx & 31;
            int row = row0 + r;
            float4 v = make_float4(0.f, 0.f, 0.f, 0.f);
            if (row < NN) {
                if (m == 0) {
                    float s = g_invt[row];
                    v = f4_scale(((const float4*)g_uout)[(size_t)row * 32 + c4], s);
                } else if (m == 1) {
                    float s = g_invs[row];
                    v = f4_scale(((const float4*)g_uin)[(size_t)row * 32 + c4], s);
                } else {
                    float4 u = ((const float4*)x)[(size_t)row * 32 + c4];
                    float4 lr = __ldg((const float4*)loop_rel + c4);
                    v = f4_sub(u, lr);
                }
            }
            ((float4*)su)[idx] = v;
        }
        __syncthreads();

        const float4* sw4 = (const float4*)(sw + m * DD * DD);
        for (int k = 0; k < DD; k += 4) {
            float4 w0 = sw4[(k + 0) * 32 + (tx ^ ((k + 0) & 31))];
            float4 w1 = sw4[(k + 1) * 32 + (tx ^ ((k + 1) & 31))];
            float4 w2 = sw4[(k + 2) * 32 + (tx ^ ((k + 2) & 31))];
            float4 w3 = sw4[(k + 3) * 32 + (tx ^ ((k + 3) & 31))];
#pragma unroll
            for (int i = 0; i < 4; i++) {
                float4 u = *(const float4*)&su[(r0 + i) * DD + k];
                acc[i][0] += u.x * w0.x + u.y * w1.x + u.z * w2.x + u.w * w3.x;
                acc[i][1] += u.x * w0.y + u.y * w1.y + u.z * w2.y + u.w * w3.y;
                acc[i][2] += u.x * w0.z + u.y * w1.z + u.z * w2.z + u.w * w3.z;
                acc[i][3] += u.x * w0.w + u.y * w1.w + u.z * w2.w + u.w * w3.w;
            }
        }
    }

    // epilogue: /3 + bias, optional relu, LayerNorm per row (warp owns 4 rows)
    float4 bb = __ldg((const float4*)bias + tx);
    float4 gg = __ldg((const float4*)lng + tx);
    float4 be = __ldg((const float4*)lnb + tx);
    const float inv3 = 1.f / 3.f;
    const float invD = 1.f / 128.f;

#pragma unroll
    for (int i = 0; i < 4; i++) {
        float v0 = acc[i][0] * inv3 + bb.x;
        float v1 = acc[i][1] * inv3 + bb.y;
        float v2 = acc[i][2] * inv3 + bb.z;
        float v3 = acc[i][3] * inv3 + bb.w;
        if (layer == 0) {
            v0 = fmaxf(v0, 0.f); v1 = fmaxf(v1, 0.f);
            v2 = fmaxf(v2, 0.f); v3 = fmaxf(v3, 0.f);
        }
        float s1 = v0 + v1 + v2 + v3;
        float s2 = v0 * v0 + v1 * v1 + v2 * v2 + v3 * v3;
#pragma unroll
        for (int off = 16; off; off >>= 1) {
            s1 += __shfl_xor_sync(0xffffffff, s1, off);
            s2 += __shfl_xor_sync(0xffffffff, s2, off);
        }
        float mu = s1 * invD;
        float var = fmaxf(s2 * invD - mu * mu, 0.f);
        float rstd = rsqrtf(var + LN_EPS);

        int row = row0 + r0 + i;
        if (row < NN) {
            float4 o;
            o.x = (v0 - mu) * rstd * gg.x + be.x;
            o.y = (v1 - mu) * rstd * gg.y + be.y;
            o.z = (v2 - mu) * rstd * gg.z + be.z;
            o.w = (v3 - mu) * rstd * gg.w + be.w;
            *(float4*)&out[(size_t)row * DD + c0] = o;
        }
    }
}

// ---------------- launch ----------------
extern "C" void kernel_launch(void* const* d_in, const int* in_sizes, int n_in,
                              void* d_out, int out_size) {
    const float* x_typeA = (const float*)d_in[0];
    const float* W_mlp   = (const float*)d_in[1];
    const float* b_mlp   = (const float*)d_in[2];
    const float* emb_B   = (const float*)d_in[3];
    const float* rel0    = (const float*)d_in[4];
    const float* lrel0   = (const float*)d_in[5];
    const float* wloop0  = (const float*)d_in[6];
    const float* win0    = (const float*)d_in[7];
    const float* wout0   = (const float*)d_in[8];
    const float* bias0   = (const float*)d_in[9];
    const float* lng0    = (const float*)d_in[10];
    const float* lnb0    = (const float*)d_in[11];
    const float* rel1    = (const float*)d_in[12];
    const float* lrel1   = (const float*)d_in[13];
    const float* wloop1  = (const float*)d_in[14];
    const float* win1    = (const float*)d_in[15];
    const float* wout1   = (const float*)d_in[16];
    const float* bias1   = (const float*)d_in[17];
    const float* lng1    = (const float*)d_in[18];
    const float* lnb1    = (const float*)d_in[19];
    const int*   esrc    = (const int*)d_in[20];
    const int*   erel    = (const int*)d_in[21];
    const int*   edst    = (const int*)d_in[22];
    float* out = (float*)d_out;

    const int smem_mlp   = (KIN * DD + 64 * KIN) * 4;       // 196608
    const int smem_fused = (3 * DD * DD + 64 * DD) * 4;     // 229376
    cudaFuncSetAttribute(k_mlp, cudaFuncAttributeMaxDynamicSharedMemorySize, smem_mlp);
    cudaFuncSetAttribute(k_fused, cudaFuncAttributeMaxDynamicSharedMemorySize, smem_fused);

    // degrees + normalization (same for both layers)
    k_zero_deg<<<(NN + 255) / 256, 256>>>();
    k_degree<<<(NE + 255) / 256, 256>>>(esrc, edst);
    k_inv<<<(NN + 255) / 256, 256>>>();

    // node encoders
    k_mlp<<<(NA + 63) / 64, 512, smem_mlp>>>(x_typeA, W_mlp, b_mlp);
    k_copyB<<<2048, 256>>>(emb_B);

    // layer 0
    k_zero_u<<<2048, 256>>>();
    k_scatter<<<NE * 32 / 256, 256>>>(0, rel0, esrc, erel, edst);
    k_fused<<<(NN + 63) / 64, 512, smem_fused>>>(0, wout0, win0, wloop0, lrel0,
                                                 bias0, lng0, lnb0, out);

    // layer 1
    k_zero_u<<<2048, 256>>>();
    k_scatter<<<NE * 32 / 256, 256>>>(1, rel1, esrc, erel, edst);
    k_fused<<<(NN + 63) / 64, 512, smem_fused>>>(1, wout1, win1, wloop1, lrel1,
                                                 bias1, lng1, lnb1, out);
}

// round 2
// speedup vs baseline: 1.1643x; 1.1643x over previous
#include <cuda_runtime.h>

#define NN 100000          // total nodes
#define NA 50000           // typeA nodes
#define DD 128             // hidden dim
#define KIN 256            // typeA input dim
#define NE 600000          // edges
#define LN_EPS 1e-5f

// ---------------- scratch (device globals: allocation-free) ----------------
__device__ __align__(16) float g_x[(size_t)NN * DD];     // layer-0 input features
__device__ __align__(16) float g_y[(size_t)NN * DD];     // layer-0 output
__device__ __align__(16) float g_uout[(size_t)NN * DD];  // aggregated out-direction (pre-scaled)
__device__ __align__(16) float g_uin[(size_t)NN * DD];   // aggregated in-direction (pre-scaled)
__device__ float g_invs[NN];
__device__ float g_invt[NN];

// CSR scratch
__device__ int g_cnt_t[NN], g_cnt_s[NN];
__device__ int g_off_t[NN], g_off_s[NN];
__device__ int g_woff_t[NN], g_woff_s[NN];
__device__ int g_list_t[NE], g_list_s[NE];   // packed: nbr | (rel<<17)
__device__ int g_bsum[512];

// ---------------- helpers ----------------
__device__ __forceinline__ float4 f4_sub(float4 a, float4 b) {
    return make_float4(a.x - b.x, a.y - b.y, a.z - b.z, a.w - b.w);
}
__device__ __forceinline__ void fma2(unsigned long long& d, unsigned long long a,
                                     unsigned long long b) {
    asm("fma.rn.f32x2 %0, %1, %2, %0;" : "+l"(d) : "l"(a), "l"(b));
}
__device__ __forceinline__ float2 unpack2(unsigned long long v) {
    float2 r;
    r.x = __uint_as_float((unsigned int)v);
    r.y = __uint_as_float((unsigned int)(v >> 32));
    return r;
}

// ================= CSR build =================
__global__ void k_csr_zero() {
    int i = blockIdx.x * blockDim.x + threadIdx.x;
    if (i < NN) { g_cnt_t[i] = 0; g_cnt_s[i] = 0; }
}

__global__ void k_hist(const int* __restrict__ s, const int* __restrict__ t) {
    int e = blockIdx.x * blockDim.x + threadIdx.x;
    if (e < NE) {
        atomicAdd(&g_cnt_t[t[e]], 1);
        atomicAdd(&g_cnt_s[s[e]], 1);
    }
}

__global__ void k_inv() {
    int i = blockIdx.x * blockDim.x + threadIdx.x;
    if (i < NN) {
        int ct = g_cnt_t[i], cs = g_cnt_s[i];
        g_invt[i] = ct > 0 ? rsqrtf((float)ct) : 0.f;
        g_invs[i] = cs > 0 ? rsqrtf((float)cs) : 0.f;
    }
}

__global__ void __launch_bounds__(512) k_scan1() {
    __shared__ int sh[512];
    int i = blockIdx.x * 512 + threadIdx.x;
    int v = (i < NN) ? g_cnt_t[i] : 0;
    sh[threadIdx.x] = v;
    __syncthreads();
    for (int o = 256; o; o >>= 1) {
        if (threadIdx.x < o) sh[threadIdx.x] += sh[threadIdx.x + o];
        __syncthreads();
    }
    if (threadIdx.x == 0) g_bsum[blockIdx.x] = sh[0];
    __syncthreads();
    int w = (i < NN) ? g_cnt_s[i] : 0;
    sh[threadIdx.x] = w;
    __syncthreads();
    for (int o = 256; o; o >>= 1) {
        if (threadIdx.x < o) sh[threadIdx.x] += sh[threadIdx.x + o];
        __syncthreads();
    }
    if (threadIdx.x == 0) g_bsum[256 + blockIdx.x] = sh[0];
}

__global__ void __launch_bounds__(256) k_scan2(int nblk) {
    __shared__ int st[256], ss[256];
    int b = threadIdx.x;
    int vt = (b < nblk) ? g_bsum[b] : 0;
    int vs = (b < nblk) ? g_bsum[256 + b] : 0;
    st[b] = vt; ss[b] = vs;
    __syncthreads();
    for (int o = 1; o < 256; o <<= 1) {
        int at = (b >= o) ? st[b - o] : 0;
        int as = (b >= o) ? ss[b - o] : 0;
        __syncthreads();
        st[b] += at; ss[b] += as;
        __syncthreads();
    }
    if (b < nblk) {
        g_bsum[b] = st[b] - vt;           // exclusive
        g_bsum[256 + b] = ss[b] - vs;
    }
}

__global__ void __launch_bounds__(512) k_scan3() {
    __shared__ int st[512], ss[512];
    int tid = threadIdx.x;
    int i = blockIdx.x * 512 + tid;
    int vt = (i < NN) ? g_cnt_t[i] : 0;
    int vs = (i < NN) ? g_cnt_s[i] : 0;
    st[tid] = vt; ss[tid] = vs;
    __syncthreads();
    for (int o = 1; o < 512; o <<= 1) {
        int at = (tid >= o) ? st[tid - o] : 0;
        int as = (tid >= o) ? ss[tid - o] : 0;
        __syncthreads();
        st[tid] += at; ss[tid] += as;
        __syncthreads();
    }
    if (i < NN) {
        int et = st[tid] - vt + g_bsum[blockIdx.x];
        int es = ss[tid] - vs + g_bsum[256 + blockIdx.x];
        g_off_t[i] = et; g_woff_t[i] = et;
        g_off_s[i] = es; g_woff_s[i] = es;
    }
}

__global__ void k_fill(const int* __restrict__ s, const int* __restrict__ r,
                       const int* __restrict__ t) {
    int e = blockIdx.x * blockDim.x + threadIdx.x;
    if (e < NE) {
        int si = s[e], ri = r[e], ti = t[e];
        int pt = atomicAdd(&g_woff_t[ti], 1);
        g_list_t[pt] = si | (ri << 17);
        int ps = atomicAdd(&g_woff_s[si], 1);
        g_list_s[ps] = ti | (ri << 17);
    }
}

// ================= typeB copy =================
__global__ void k_copyB(const float* __restrict__ embB) {
    int n = NA * DD / 4;
    float4* dst = (float4*)(g_x + (size_t)NA * DD);
    const float4* src = (const float4*)embB;
    for (int i = blockIdx.x * blockDim.x + threadIdx.x; i < n;
         i += gridDim.x * blockDim.x) {
        dst[i] = src[i];
    }
}

// ================= gather-aggregate (one warp per node) =================
// uout[n] = invt[n] * sum_{e: dst=n} invs[s]*(x[s]-rel[r])
// uin[n]  = invs[n] * sum_{e: src=n} invt[t]*(x[t]-rel[r])
__global__ void __launch_bounds__(256) k_gather(int layer, const float* __restrict__ rel) {
    __shared__ float srel[32 * DD];
    int tid = threadIdx.x;
    for (int i = tid; i < 32 * DD; i += 256) srel[i] = rel[i];
    __syncthreads();

    int n = blockIdx.x * 8 + (tid >> 5);
    int lane = tid & 31;
    const float* x = layer ? g_y : g_x;
    const float4* x4 = (const float4*)x;

    // out direction (in-edges by dst)
    {
        float4 acc = make_float4(0.f, 0.f, 0.f, 0.f);
        int beg = g_off_t[n];
        int cnt = g_cnt_t[n];
        for (int j = 0; j < cnt; j++) {
            int val = __ldg(g_list_t + beg + j);
            int s = val & 131071;
            int r = val >> 17;
            float ws = __ldg(g_invs + s);
            float4 xv = __ldg(x4 + (size_t)s * 32 + lane);
            float4 rv = *(const float4*)&srel[r * DD + lane * 4];
            acc.x = fmaf(ws, xv.x - rv.x, acc.x);
            acc.y = fmaf(ws, xv.y - rv.y, acc.y);
            acc.z = fmaf(ws, xv.z - rv.z, acc.z);
            acc.w = fmaf(ws, xv.w - rv.w, acc.w);
        }
        float sc = g_invt[n];
        float4 o = make_float4(acc.x * sc, acc.y * sc, acc.z * sc, acc.w * sc);
        ((float4*)g_uout)[(size_t)n * 32 + lane] = o;
    }
    // in direction (out-edges by src)
    {
        float4 acc = make_float4(0.f, 0.f, 0.f, 0.f);
        int beg = g_off_s[n];
        int cnt = g_cnt_s[n];
        for (int j = 0; j < cnt; j++) {
            int val = __ldg(g_list_s + beg + j);
            int t = val & 131071;
            int r = val >> 17;
            float wt = __ldg(g_invt + t);
            float4 xv = __ldg(x4 + (size_t)t * 32 + lane);
            float4 rv = *(const float4*)&srel[r * DD + lane * 4];
            acc.x = fmaf(wt, xv.x - rv.x, acc.x);
            acc.y = fmaf(wt, xv.y - rv.y, acc.y);
            acc.z = fmaf(wt, xv.z - rv.z, acc.z);
            acc.w = fmaf(wt, xv.w - rv.w, acc.w);
        }
        float sc = g_invs[n];
        float4 o = make_float4(acc.x * sc, acc.y * sc, acc.z * sc, acc.w * sc);
        ((float4*)g_uin)[(size_t)n * 32 + lane] = o;
    }
}

// ================= MLP: g_x[0:NA] = X @ W^T + b (f32x2 packed) =================
// 512 threads, 128-row tile, K=256 in two staged halves.
// smem: sw (128x128 f32 swizzled, 64KB) + su (128x128 duplicated f32x2, 128KB)
__global__ void __launch_bounds__(512) k_mlp(const float* __restrict__ X,
                                             const float* __restrict__ W,
                                             const float* __restrict__ b) {
    extern __shared__ float sm[];
    float* sw = sm;                                      // 16384 floats
    unsigned long long* su = (unsigned long long*)(sm + 16384);  // 16384 ull

    int tid = threadIdx.x;
    int tx = tid & 31, ty = tid >> 5;
    int c0 = tx * 4, r0 = ty * 8;
    int row0 = blockIdx.x * 128;

    unsigned long long acc[8][2];
#pragma unroll
    for (int i = 0; i < 8; i++) { acc[i][0] = 0ull; acc[i][1] = 0ull; }

    for (int kh = 0; kh < 2; kh++) {
        __syncthreads();
        // weights: W[o][kh*128+k] -> sw_t[k][o] with 4-col-group XOR swizzle
        for (int idx = tid; idx < DD * DD; idx += 512) {
            int o = idx >> 7, k = idx & 127;
            int j = o >> 2, sub = o & 3;
            sw[k * DD + (((j ^ (k & 31)) << 2) + sub)] = W[o * KIN + kh * DD + k];
        }
        // input tile, duplicated
        for (int idx = tid; idx < 128 * 32; idx += 512) {
            int r = idx >> 5, c4 = idx & 31;
            int row = row0 + r;
            float4 v = make_float4(0.f, 0.f, 0.f, 0.f);
            if (row < NA) v = ((const float4*)X)[(size_t)row * 64 + kh * 32 + c4];
            float2* sp = (float2*)&su[r * DD + c4 * 4];
            sp[0] = make_float2(v.x, v.x);
            sp[1] = make_float2(v.y, v.y);
            sp[2] = make_float2(v.z, v.z);
            sp[3] = make_float2(v.w, v.w);
        }
        __syncthreads();

#pragma unroll 4
        for (int k = 0; k < DD; k += 2) {
            ulonglong2 wa = *(const ulonglong2*)&sw[k * DD + ((tx ^ (k & 31)) << 2)];
            ulonglong2 wb = *(const ulonglong2*)&sw[(k + 1) * DD + ((tx ^ ((k + 1) & 31)) << 2)];
#pragma unroll
            for (int i = 0; i < 8; i++) {
                ulonglong2 u = *(const ulonglong2*)&su[(r0 + i) * DD + k];
                fma2(acc[i][0], u.x, wa.x);
                fma2(acc[i][1], u.x, wa.y);
                fma2(acc[i][0], u.y, wb.x);
                fma2(acc[i][1], u.y, wb.y);
            }
        }
    }

    float4 bb = __ldg((const float4*)b + tx);
#pragma unroll
    for (int i = 0; i < 8; i++) {
        int row = row0 + r0 + i;
        if (row < NA) {
            float2 p0 = unpack2(acc[i][0]);
            float2 p1 = unpack2(acc[i][1]);
            float4 o = make_float4(p0.x + bb.x, p0.y + bb.y, p1.x + bb.z, p1.y + bb.w);
            *(float4*)&g_x[(size_t)row * DD + c0] = o;
        }
    }
}

// ================= fused conv (f32x2): 3 matmuls + bias + relu? + LN ==========
// 512 threads, 128-row tile; per-m staged weights.
__global__ void __launch_bounds__(512) k_fused(
    int layer, const float* __restrict__ Wout, const float* __restrict__ Win,
    const float* __restrict__ Wloop, const float* __restrict__ loop_rel,
    const float* __restrict__ bias, const float* __restrict__ lng,
    const float* __restrict__ lnb, float* __restrict__ dout) {
    extern __shared__ float sm[];
    float* sw = sm;                                      // 16384 floats
    unsigned long long* su = (unsigned long long*)(sm + 16384);  // 16384 ull

    int tid = threadIdx.x;
    int tx = tid & 31, ty = tid >> 5;
    int c0 = tx * 4, r0 = ty * 8;
    int row0 = blockIdx.x * 128;
    const float* x = layer ? g_y : g_x;
    float* out = layer ? dout : g_y;

    unsigned long long acc[8][2];
#pragma unroll
    for (int i = 0; i < 8; i++) { acc[i][0] = 0ull; acc[i][1] = 0ull; }

    for (int m = 0; m < 3; m++) {
        const float* W = (m == 0) ? Wout : (m == 1) ? Win : Wloop;
        __syncthreads();
        for (int idx = tid; idx < DD * DD; idx += 512) {
            int o = idx >> 7, k = idx & 127;
            int j = o >> 2, sub = o & 3;
            sw[k * DD + (((j ^ (k & 31)) << 2) + sub)] = W[idx];
        }
        for (int idx = tid; idx < 128 * 32; idx += 512) {
            int r = idx >> 5, c4 = idx & 31;
            int row = row0 + r;
            float4 v = make_float4(0.f, 0.f, 0.f, 0.f);
            if (row < NN) {
                if (m == 0) {
                    v = ((const float4*)g_uout)[(size_t)row * 32 + c4];
                } else if (m == 1) {
                    v = ((const float4*)g_uin)[(size_t)row * 32 + c4];
                } else {
                    float4 u = ((const float4*)x)[(size_t)row * 32 + c4];
                    float4 lr = __ldg((const float4*)loop_rel + c4);
                    v = f4_sub(u, lr);
                }
            }
            float2* sp = (float2*)&su[r * DD + c4 * 4];
            sp[0] = make_float2(v.x, v.x);
            sp[1] = make_float2(v.y, v.y);
            sp[2] = make_float2(v.z, v.z);
            sp[3] = make_float2(v.w, v.w);
        }
        __syncthreads();

#pragma unroll 4
        for (int k = 0; k < DD; k += 2) {
            ulonglong2 wa = *(const ulonglong2*)&sw[k * DD + ((tx ^ (k & 31)) << 2)];
            ulonglong2 wb = *(const ulonglong2*)&sw[(k + 1) * DD + ((tx ^ ((k + 1) & 31)) << 2)];
#pragma unroll
            for (int i = 0; i < 8; i++) {
                ulonglong2 u = *(const ulonglong2*)&su[(r0 + i) * DD + k];
                fma2(acc[i][0], u.x, wa.x);
                fma2(acc[i][1], u.x, wa.y);
                fma2(acc[i][0], u.y, wb.x);
                fma2(acc[i][1], u.y, wb.y);
            }
        }
    }

    // epilogue: /3 + bias, relu (layer 0), LayerNorm per row
    float4 bb = __ldg((const float4*)bias + tx);
    float4 gg = __ldg((const float4*)lng + tx);
    float4 be = __ldg((const float4*)lnb + tx);
    const float inv3 = 1.f / 3.f;
    const float invD = 1.f / 128.f;

#pragma unroll
    for (int i = 0; i < 8; i++) {
        float2 p0 = unpack2(acc[i][0]);
        float2 p1 = unpack2(acc[i][1]);
        float v0 = p0.x * inv3 + bb.x;
        float v1 = p0.y * inv3 + bb.y;
        float v2 = p1.x * inv3 + bb.z;
        float v3 = p1.y * inv3 + bb.w;
        if (layer == 0) {
            v0 = fmaxf(v0, 0.f); v1 = fmaxf(v1, 0.f);
            v2 = fmaxf(v2, 0.f); v3 = fmaxf(v3, 0.f);
        }
        float s1 = v0 + v1 + v2 + v3;
        float s2 = v0 * v0 + v1 * v1 + v2 * v2 + v3 * v3;
#pragma unroll
        for (int off = 16; off; off >>= 1) {
            s1 += __shfl_xor_sync(0xffffffff, s1, off);
            s2 += __shfl_xor_sync(0xffffffff, s2, off);
        }
        float mu = s1 * invD;
        float var = fmaxf(s2 * invD - mu * mu, 0.f);
        float rstd = rsqrtf(var + LN_EPS);

        int row = row0 + r0 + i;
        if (row < NN) {
            float4 o;
            o.x = (v0 - mu) * rstd * gg.x + be.x;
            o.y = (v1 - mu) * rstd * gg.y + be.y;
            o.z = (v2 - mu) * rstd * gg.z + be.z;
            o.w = (v3 - mu) * rstd * gg.w + be.w;
            *(float4*)&out[(size_t)row * DD + c0] = o;
        }
    }
}

// ================= launch =================
extern "C" void kernel_launch(void* const* d_in, const int* in_sizes, int n_in,
                              void* d_out, int out_size) {
    const float* x_typeA = (const float*)d_in[0];
    const float* W_mlp   = (const float*)d_in[1];
    const float* b_mlp   = (const float*)d_in[2];
    const float* emb_B   = (const float*)d_in[3];
    const float* rel0    = (const float*)d_in[4];
    const float* lrel0   = (const float*)d_in[5];
    const float* wloop0  = (const float*)d_in[6];
    const float* win0    = (const float*)d_in[7];
    const float* wout0   = (const float*)d_in[8];
    const float* bias0   = (const float*)d_in[9];
    const float* lng0    = (const float*)d_in[10];
    const float* lnb0    = (const float*)d_in[11];
    const float* rel1    = (const float*)d_in[12];
    const float* lrel1   = (const float*)d_in[13];
    const float* wloop1  = (const float*)d_in[14];
    const float* win1    = (const float*)d_in[15];
    const float* wout1   = (const float*)d_in[16];
    const float* bias1   = (const float*)d_in[17];
    const float* lng1    = (const float*)d_in[18];
    const float* lnb1    = (const float*)d_in[19];
    const int*   esrc    = (const int*)d_in[20];
    const int*   erel    = (const int*)d_in[21];
    const int*   edst    = (const int*)d_in[22];
    float* out = (float*)d_out;

    const int smem_big = 16384 * 4 + 16384 * 8;   // 196608
    cudaFuncSetAttribute(k_mlp, cudaFuncAttributeMaxDynamicSharedMemorySize, smem_big);
    cudaFuncSetAttribute(k_fused, cudaFuncAttributeMaxDynamicSharedMemorySize, smem_big);

    const int nScanBlk = (NN + 511) / 512;   // 196

    // CSR build (shared by both layers)
    k_csr_zero<<<(NN + 255) / 256, 256>>>();
    k_hist<<<(NE + 255) / 256, 256>>>(esrc, edst);
    k_inv<<<(NN + 255) / 256, 256>>>();
    k_scan1<<<nScanBlk, 512>>>();
    k_scan2<<<1, 256>>>(nScanBlk);
    k_scan3<<<nScanBlk, 512>>>();
    k_fill<<<(NE + 255) / 256, 256>>>(esrc, erel, edst);

    // node encoders
    k_mlp<<<(NA + 127) / 128, 512, smem_big>>>(x_typeA, W_mlp, b_mlp);
    k_copyB<<<2048, 256>>>(emb_B);

    // layer 0
    k_gather<<<NN / 8, 256>>>(0, rel0);
    k_fused<<<(NN + 127) / 128, 512, smem_big>>>(0, wout0, win0, wloop0, lrel0,
                                                 bias0, lng0, lnb0, out);
    // layer 1
    k_gather<<<NN / 8, 256>>>(1, rel1);
    k_fused<<<(NN + 127) / 128, 512, smem_big>>>(1, wout1, win1, wloop1, lrel1,
                                                 bias1, lng1, lnb1, out);
}

// round 3
// speedup vs baseline: 1.4237x; 1.2228x over previous
#include <cuda_runtime.h>

#define NN 100000          // total nodes
#define NA 50000           // typeA nodes
#define DD 128             // hidden dim
#define KIN 256            // typeA input dim
#define NE 600000          // edges
#define LN_EPS 1e-5f
#define CHUNK 64           // K staging chunk

// ---------------- scratch ----------------
__device__ __align__(16) float g_x[(size_t)NN * DD];
__device__ __align__(16) float g_y[(size_t)NN * DD];
__device__ __align__(16) float g_uout[(size_t)NN * DD];
__device__ __align__(16) float g_uin[(size_t)NN * DD];
__device__ float g_invs[NN];
__device__ float g_invt[NN];

__device__ int g_cnt_t[NN], g_cnt_s[NN];
__device__ int g_off_t[NN], g_off_s[NN];
__device__ int g_woff_t[NN], g_woff_s[NN];
__device__ int g_list_t[NE], g_list_s[NE];
__device__ int g_bsum[512];

// ---------------- helpers ----------------
__device__ __forceinline__ void fma2(unsigned long long& d, unsigned long long a,
                                     unsigned long long b) {
    asm("fma.rn.f32x2 %0, %1, %2, %0;" : "+l"(d) : "l"(a), "l"(b));
}
__device__ __forceinline__ float2 unpack2(unsigned long long v) {
    float2 r;
    r.x = __uint_as_float((unsigned int)v);
    r.y = __uint_as_float((unsigned int)(v >> 32));
    return r;
}

// ================= CSR build =================
__global__ void k_csr_zero() {
    int i = blockIdx.x * blockDim.x + threadIdx.x;
    if (i < NN) { g_cnt_t[i] = 0; g_cnt_s[i] = 0; }
}

__global__ void k_hist(const int* __restrict__ s, const int* __restrict__ t) {
    int e = blockIdx.x * blockDim.x + threadIdx.x;
    if (e < NE) {
        atomicAdd(&g_cnt_t[t[e]], 1);
        atomicAdd(&g_cnt_s[s[e]], 1);
    }
}

__global__ void __launch_bounds__(512) k_scan1() {
    __shared__ int sh[512];
    int i = blockIdx.x * 512 + threadIdx.x;
    int v = (i < NN) ? g_cnt_t[i] : 0;
    sh[threadIdx.x] = v;
    __syncthreads();
    for (int o = 256; o; o >>= 1) {
        if (threadIdx.x < o) sh[threadIdx.x] += sh[threadIdx.x + o];
        __syncthreads();
    }
    if (threadIdx.x == 0) g_bsum[blockIdx.x] = sh[0];
    __syncthreads();
    int w = (i < NN) ? g_cnt_s[i] : 0;
    sh[threadIdx.x] = w;
    __syncthreads();
    for (int o = 256; o; o >>= 1) {
        if (threadIdx.x < o) sh[threadIdx.x] += sh[threadIdx.x + o];
        __syncthreads();
    }
    if (threadIdx.x == 0) g_bsum[256 + blockIdx.x] = sh[0];
}

__global__ void __launch_bounds__(256) k_scan2(int nblk) {
    __shared__ int st[256], ss[256];
    int b = threadIdx.x;
    int vt = (b < nblk) ? g_bsum[b] : 0;
    int vs = (b < nblk) ? g_bsum[256 + b] : 0;
    st[b] = vt; ss[b] = vs;
    __syncthreads();
    for (int o = 1; o < 256; o <<= 1) {
        int at = (b >= o) ? st[b - o] : 0;
        int as = (b >= o) ? ss[b - o] : 0;
        __syncthreads();
        st[b] += at; ss[b] += as;
        __syncthreads();
    }
    if (b < nblk) {
        g_bsum[b] = st[b] - vt;
        g_bsum[256 + b] = ss[b] - vs;
    }
}

// scan3 + inv fused
__global__ void __launch_bounds__(512) k_scan3() {
    __shared__ int st[512], ss[512];
    int tid = threadIdx.x;
    int i = blockIdx.x * 512 + tid;
    int vt = (i < NN) ? g_cnt_t[i] : 0;
    int vs = (i < NN) ? g_cnt_s[i] : 0;
    st[tid] = vt; ss[tid] = vs;
    __syncthreads();
    for (int o = 1; o < 512; o <<= 1) {
        int at = (tid >= o) ? st[tid - o] : 0;
        int as = (tid >= o) ? ss[tid - o] : 0;
        __syncthreads();
        st[tid] += at; ss[tid] += as;
        __syncthreads();
    }
    if (i < NN) {
        int et = st[tid] - vt + g_bsum[blockIdx.x];
        int es = ss[tid] - vs + g_bsum[256 + blockIdx.x];
        g_off_t[i] = et; g_woff_t[i] = et;
        g_off_s[i] = es; g_woff_s[i] = es;
        g_invt[i] = vt > 0 ? rsqrtf((float)vt) : 0.f;
        g_invs[i] = vs > 0 ? rsqrtf((float)vs) : 0.f;
    }
}

__global__ void k_fill(const int* __restrict__ s, const int* __restrict__ r,
                       const int* __restrict__ t) {
    int e = blockIdx.x * blockDim.x + threadIdx.x;
    if (e < NE) {
        int si = s[e], ri = r[e], ti = t[e];
        int pt = atomicAdd(&g_woff_t[ti], 1);
        g_list_t[pt] = si | (ri << 17);
        int ps = atomicAdd(&g_woff_s[si], 1);
        g_list_s[ps] = ti | (ri << 17);
    }
}

__global__ void k_copyB(const float* __restrict__ embB) {
    int n = NA * DD / 4;
    float4* dst = (float4*)(g_x + (size_t)NA * DD);
    const float4* src = (const float4*)embB;
    for (int i = blockIdx.x * blockDim.x + threadIdx.x; i < n;
         i += gridDim.x * blockDim.x) {
        dst[i] = src[i];
    }
}

// ================= gather-aggregate =================
// 256 threads, 8 warps, 4 nodes per warp => 32 nodes/block
__global__ void __launch_bounds__(256) k_gather(int layer, const float* __restrict__ rel) {
    __shared__ float srel[32 * DD];
    int tid = threadIdx.x;
    for (int i = tid; i < 32 * DD; i += 256) srel[i] = rel[i];
    __syncthreads();

    int lane = tid & 31;
    int warp = tid >> 5;
    const float4* x4 = (const float4*)(layer ? g_y : g_x);

#pragma unroll
    for (int nd = 0; nd < 4; nd++) {
        int n = blockIdx.x * 32 + warp * 4 + nd;

        // ---- out direction (in-edges by dst) ----
        {
            float4 a0 = make_float4(0.f, 0.f, 0.f, 0.f);
            float4 a1 = make_float4(0.f, 0.f, 0.f, 0.f);
            int beg = g_off_t[n];
            int cnt = g_cnt_t[n];
            int j = 0;
            for (; j + 2 <= cnt; j += 2) {
                int v0 = __ldg(g_list_t + beg + j);
                int v1 = __ldg(g_list_t + beg + j + 1);
                int s0 = v0 & 131071, r0 = v0 >> 17;
                int s1 = v1 & 131071, r1 = v1 >> 17;
                float w0 = __ldg(g_invs + s0);
                float w1 = __ldg(g_invs + s1);
                float4 x0 = __ldg(x4 + (size_t)s0 * 32 + lane);
                float4 x1 = __ldg(x4 + (size_t)s1 * 32 + lane);
                float4 q0 = *(const float4*)&srel[r0 * DD + lane * 4];
                float4 q1 = *(const float4*)&srel[r1 * DD + lane * 4];
                a0.x = fmaf(w0, x0.x - q0.x, a0.x);
                a0.y = fmaf(w0, x0.y - q0.y, a0.y);
                a0.z = fmaf(w0, x0.z - q0.z, a0.z);
                a0.w = fmaf(w0, x0.w - q0.w, a0.w);
                a1.x = fmaf(w1, x1.x - q1.x, a1.x);
                a1.y = fmaf(w1, x1.y - q1.y, a1.y);
                a1.z = fmaf(w1, x1.z - q1.z, a1.z);
                a1.w = fmaf(w1, x1.w - q1.w, a1.w);
            }
            if (j < cnt) {
                int v0 = __ldg(g_list_t + beg + j);
                int s0 = v0 & 131071, r0 = v0 >> 17;
                float w0 = __ldg(g_invs + s0);
                float4 x0 = __ldg(x4 + (size_t)s0 * 32 + lane);
                float4 q0 = *(const float4*)&srel[r0 * DD + lane * 4];
                a0.x = fmaf(w0, x0.x - q0.x, a0.x);
                a0.y = fmaf(w0, x0.y - q0.y, a0.y);
                a0.z = fmaf(w0, x0.z - q0.z, a0.z);
                a0.w = fmaf(w0, x0.w - q0.w, a0.w);
            }
            float sc = g_invt[n];
            float4 o = make_float4((a0.x + a1.x) * sc, (a0.y + a1.y) * sc,
                                   (a0.z + a1.z) * sc, (a0.w + a1.w) * sc);
            ((float4*)g_uout)[(size_t)n * 32 + lane] = o;
        }
        // ---- in direction (out-edges by src) ----
        {
            float4 a0 = make_float4(0.f, 0.f, 0.f, 0.f);
            float4 a1 = make_float4(0.f, 0.f, 0.f, 0.f);
            int beg = g_off_s[n];
            int cnt = g_cnt_s[n];
            int j = 0;
            for (; j + 2 <= cnt; j += 2) {
                int v0 = __ldg(g_list_s + beg + j);
                int v1 = __ldg(g_list_s + beg + j + 1);
                int t0 = v0 & 131071, r0 = v0 >> 17;
                int t1 = v1 & 131071, r1 = v1 >> 17;
                float w0 = __ldg(g_invt + t0);
                float w1 = __ldg(g_invt + t1);
                float4 x0 = __ldg(x4 + (size_t)t0 * 32 + lane);
                float4 x1 = __ldg(x4 + (size_t)t1 * 32 + lane);
                float4 q0 = *(const float4*)&srel[r0 * DD + lane * 4];
                float4 q1 = *(const float4*)&srel[r1 * DD + lane * 4];
                a0.x = fmaf(w0, x0.x - q0.x, a0.x);
                a0.y = fmaf(w0, x0.y - q0.y, a0.y);
                a0.z = fmaf(w0, x0.z - q0.z, a0.z);
                a0.w = fmaf(w0, x0.w - q0.w, a0.w);
                a1.x = fmaf(w1, x1.x - q1.x, a1.x);
                a1.y = fmaf(w1, x1.y - q1.y, a1.y);
                a1.z = fmaf(w1, x1.z - q1.z, a1.z);
                a1.w = fmaf(w1, x1.w - q1.w, a1.w);
            }
            if (j < cnt) {
                int v0 = __ldg(g_list_s + beg + j);
                int t0 = v0 & 131071, r0 = v0 >> 17;
                float w0 = __ldg(g_invt + t0);
                float4 x0 = __ldg(x4 + (size_t)t0 * 32 + lane);
                float4 q0 = *(const float4*)&srel[r0 * DD + lane * 4];
                a0.x = fmaf(w0, x0.x - q0.x, a0.x);
                a0.y = fmaf(w0, x0.y - q0.y, a0.y);
                a0.z = fmaf(w0, x0.z - q0.z, a0.z);
                a0.w = fmaf(w0, x0.w - q0.w, a0.w);
            }
            float sc = g_invs[n];
            float4 o = make_float4((a0.x + a1.x) * sc, (a0.y + a1.y) * sc,
                                   (a0.z + a1.z) * sc, (a0.w + a1.w) * sc);
            ((float4*)g_uin)[(size_t)n * 32 + lane] = o;
        }
    }
}

// ================= MLP: g_x[0:NA] = X @ W^T + b =================
// 256 threads, 64-row tile, KIN staged in 4 chunks of 64. 64KB smem -> 3 CTAs/SM.
__global__ void __launch_bounds__(256, 3) k_mlp(const float* __restrict__ X,
                                                const float* __restrict__ W,
                                                const float* __restrict__ b) {
    extern __shared__ float sm[];
    float* sw = sm;                                          // 64*128 floats (32KB)
    unsigned long long* su = (unsigned long long*)(sm + CHUNK * DD);  // 64*64 ull (32KB)

    int tid = threadIdx.x;
    int tx = tid & 31, ty = tid >> 5;
    int c0 = tx * 4, r0 = ty * 8;
    int row0 = blockIdx.x * 64;

    unsigned long long acc[8][2];
#pragma unroll
    for (int i = 0; i < 8; i++) { acc[i][0] = 0ull; acc[i][1] = 0ull; }

    for (int kc = 0; kc < KIN / CHUNK; kc++) {
        __syncthreads();
        // weights: W[o][kc*64+k] -> sw[k][swz(o,k)]
        for (int idx = tid; idx < DD * CHUNK; idx += 256) {
            int o = idx >> 6, k = idx & 63;
            int j = o >> 2, sub = o & 3;
            sw[k * DD + (((j ^ (k & 31)) << 2) + sub)] = W[o * KIN + kc * CHUNK + k];
        }
        // input tile, duplicated f32x2
        for (int idx = tid; idx < 64 * (CHUNK / 4); idx += 256) {
            int r = idx >> 4, c4 = idx & 15;
            int row = row0 + r;
            float4 v = make_float4(0.f, 0.f, 0.f, 0.f);
            if (row < NA) v = ((const float4*)X)[(size_t)row * (KIN / 4) + kc * 16 + c4];
            float2* sp = (float2*)&su[r * CHUNK + c4 * 4];
            sp[0] = make_float2(v.x, v.x);
            sp[1] = make_float2(v.y, v.y);
            sp[2] = make_float2(v.z, v.z);
            sp[3] = make_float2(v.w, v.w);
        }
        __syncthreads();

#pragma unroll 4
        for (int k = 0; k < CHUNK; k += 2) {
            ulonglong2 wa = *(const ulonglong2*)&sw[k * DD + ((tx ^ (k & 31)) << 2)];
            ulonglong2 wb = *(const ulonglong2*)&sw[(k + 1) * DD + ((tx ^ ((k + 1) & 31)) << 2)];
#pragma unroll
            for (int i = 0; i < 8; i++) {
                ulonglong2 u = *(const ulonglong2*)&su[(r0 + i) * CHUNK + k];
                fma2(acc[i][0], u.x, wa.x);
                fma2(acc[i][1], u.x, wa.y);
                fma2(acc[i][0], u.y, wb.x);
                fma2(acc[i][1], u.y, wb.y);
            }
        }
    }

    float4 bb = __ldg((const float4*)b + tx);
#pragma unroll
    for (int i = 0; i < 8; i++) {
        int row = row0 + r0 + i;
        if (row < NA) {
            float2 p0 = unpack2(acc[i][0]);
            float2 p1 = unpack2(acc[i][1]);
            float4 o = make_float4(p0.x + bb.x, p0.y + bb.y, p1.x + bb.z, p1.y + bb.w);
            *(float4*)&g_x[(size_t)row * DD + c0] = o;
        }
    }
}

// ================= fused conv =================
// 256 threads, 64-row tile, 6 stages (3 matrices x 2 K-chunks). 64KB smem -> 3 CTAs/SM.
__global__ void __launch_bounds__(256, 3) k_fused(
    int layer, const float* __restrict__ Wout, const float* __restrict__ Win,
    const float* __restrict__ Wloop, const float* __restrict__ loop_rel,
    const float* __restrict__ bias, const float* __restrict__ lng,
    const float* __restrict__ lnb, float* __restrict__ dout) {
    extern __shared__ float sm[];
    float* sw = sm;
    unsigned long long* su = (unsigned long long*)(sm + CHUNK * DD);

    int tid = threadIdx.x;
    int tx = tid & 31, ty = tid >> 5;
    int c0 = tx * 4, r0 = ty * 8;
    int row0 = blockIdx.x * 64;
    const float4* x4 = (const float4*)(layer ? g_y : g_x);
    float* out = layer ? dout : g_y;

    unsigned long long acc[8][2];
#pragma unroll
    for (int i = 0; i < 8; i++) { acc[i][0] = 0ull; acc[i][1] = 0ull; }

    for (int st = 0; st < 6; st++) {
        int m = st >> 1;          // matrix index
        int kc = st & 1;          // K-chunk
        const float* W = (m == 0) ? Wout : (m == 1) ? Win : Wloop;
        __syncthreads();
        for (int idx = tid; idx < DD * CHUNK; idx += 256) {
            int o = idx >> 6, k = idx & 63;
            int j = o >> 2, sub = o & 3;
            sw[k * DD + (((j ^ (k & 31)) << 2) + sub)] = W[o * DD + kc * CHUNK + k];
        }
        for (int idx = tid; idx < 64 * (CHUNK / 4); idx += 256) {
            int r = idx >> 4, c4 = idx & 15;
            int row = row0 + r;
            int gc4 = kc * 16 + c4;
            float4 v = make_float4(0.f, 0.f, 0.f, 0.f);
            if (row < NN) {
                if (m == 0) {
                    v = ((const float4*)g_uout)[(size_t)row * 32 + gc4];
                } else if (m == 1) {
                    v = ((const float4*)g_uin)[(size_t)row * 32 + gc4];
                } else {
                    float4 u = x4[(size_t)row * 32 + gc4];
                    float4 lr = __ldg((const float4*)loop_rel + gc4);
                    v = make_float4(u.x - lr.x, u.y - lr.y, u.z - lr.z, u.w - lr.w);
                }
            }
            float2* sp = (float2*)&su[r * CHUNK + c4 * 4];
            sp[0] = make_float2(v.x, v.x);
            sp[1] = make_float2(v.y, v.y);
            sp[2] = make_float2(v.z, v.z);
            sp[3] = make_float2(v.w, v.w);
        }
        __syncthreads();

#pragma unroll 4
        for (int k = 0; k < CHUNK; k += 2) {
            ulonglong2 wa = *(const ulonglong2*)&sw[k * DD + ((tx ^ (k & 31)) << 2)];
            ulonglong2 wb = *(const ulonglong2*)&sw[(k + 1) * DD + ((tx ^ ((k + 1) & 31)) << 2)];
#pragma unroll
            for (int i = 0; i < 8; i++) {
                ulonglong2 u = *(const ulonglong2*)&su[(r0 + i) * CHUNK + k];
                fma2(acc[i][0], u.x, wa.x);
                fma2(acc[i][1], u.x, wa.y);
                fma2(acc[i][0], u.y, wb.x);
                fma2(acc[i][1], u.y, wb.y);
            }
        }
    }

    // epilogue: /3 + bias, relu (layer 0), LayerNorm per row
    float4 bb = __ldg((const float4*)bias + tx);
    float4 gg = __ldg((const float4*)lng + tx);
    float4 be = __ldg((const float4*)lnb + tx);
    const float inv3 = 1.f / 3.f;
    const float invD = 1.f / 128.f;

#pragma unroll
    for (int i = 0; i < 8; i++) {
        float2 p0 = unpack2(acc[i][0]);
        float2 p1 = unpack2(acc[i][1]);
        float v0 = p0.x * inv3 + bb.x;
        float v1 = p0.y * inv3 + bb.y;
        float v2 = p1.x * inv3 + bb.z;
        float v3 = p1.y * inv3 + bb.w;
        if (layer == 0) {
            v0 = fmaxf(v0, 0.f); v1 = fmaxf(v1, 0.f);
            v2 = fmaxf(v2, 0.f); v3 = fmaxf(v3, 0.f);
        }
        float s1 = v0 + v1 + v2 + v3;
        float s2 = v0 * v0 + v1 * v1 + v2 * v2 + v3 * v3;
#pragma unroll
        for (int off = 16; off; off >>= 1) {
            s1 += __shfl_xor_sync(0xffffffff, s1, off);
            s2 += __shfl_xor_sync(0xffffffff, s2, off);
        }
        float mu = s1 * invD;
        float var = fmaxf(s2 * invD - mu * mu, 0.f);
        float rstd = rsqrtf(var + LN_EPS);

        int row = row0 + r0 + i;
        if (row < NN) {
            float4 o;
            o.x = (v0 - mu) * rstd * gg.x + be.x;
            o.y = (v1 - mu) * rstd * gg.y + be.y;
            o.z = (v2 - mu) * rstd * gg.z + be.z;
            o.w = (v3 - mu) * rstd * gg.w + be.w;
            *(float4*)&out[(size_t)row * DD + c0] = o;
        }
    }
}

// ================= launch =================
extern "C" void kernel_launch(void* const* d_in, const int* in_sizes, int n_in,
                              void* d_out, int out_size) {
    const float* x_typeA = (const float*)d_in[0];
    const float* W_mlp   = (const float*)d_in[1];
    const float* b_mlp   = (const float*)d_in[2];
    const float* emb_B   = (const float*)d_in[3];
    const float* rel0    = (const float*)d_in[4];
    const float* lrel0   = (const float*)d_in[5];
    const float* wloop0  = (const float*)d_in[6];
    const float* win0    = (const float*)d_in[7];
    const float* wout0   = (const float*)d_in[8];
    const float* bias0   = (const float*)d_in[9];
    const float* lng0    = (const float*)d_in[10];
    const float* lnb0    = (const float*)d_in[11];
    const float* rel1    = (const float*)d_in[12];
    const float* lrel1   = (const float*)d_in[13];
    const float* wloop1  = (const float*)d_in[14];
    const float* win1    = (const float*)d_in[15];
    const float* wout1   = (const float*)d_in[16];
    const float* bias1   = (const float*)d_in[17];
    const float* lng1    = (const float*)d_in[18];
    const float* lnb1    = (const float*)d_in[19];
    const int*   esrc    = (const int*)d_in[20];
    const int*   erel    = (const int*)d_in[21];
    const int*   edst    = (const int*)d_in[22];
    float* out = (float*)d_out;

    const int smem = CHUNK * DD * 4 + 64 * CHUNK * 8;   // 32KB + 32KB = 65536
    cudaFuncSetAttribute(k_mlp, cudaFuncAttributeMaxDynamicSharedMemorySize, smem);
    cudaFuncSetAttribute(k_fused, cudaFuncAttributeMaxDynamicSharedMemorySize, smem);

    const int nScanBlk = (NN + 511) / 512;   // 196

    // 1-5: CSR prefix (inv fused into scan3)
    k_csr_zero<<<(NN + 255) / 256, 256>>>();
    k_hist<<<(NE + 255) / 256, 256>>>(esrc, edst);
    k_scan1<<<nScanBlk, 512>>>();
    k_scan2<<<1, 256>>>(nScanBlk);
    k_scan3<<<nScanBlk, 512>>>();

    // 6: mlp (profiled by ncu -s 5 -c 1)
    k_mlp<<<(NA + 63) / 64, 256, smem>>>(x_typeA, W_mlp, b_mlp);

    // 7-8
    k_fill<<<(NE + 255) / 256, 256>>>(esrc, erel, edst);
    k_copyB<<<2048, 256>>>(emb_B);

    // layer 0
    k_gather<<<NN / 32, 256>>>(0, rel0);
    k_fused<<<(NN + 63) / 64, 256, smem>>>(0, wout0, win0, wloop0, lrel0,
                                           bias0, lng0, lnb0, out);
    // layer 1
    k_gather<<<NN / 32, 256>>>(1, rel1);
    k_fused<<<(NN + 63) / 64, 256, smem>>>(1, wout1, win1, wloop1, lrel1,
                                           bias1, lng1, lnb1, out);
}

// round 5
// speedup vs baseline: 1.5021x; 1.0551x over previous
#include <cuda_runtime.h>
#include <cstdint>

#define NN 100000
#define NA 50000
#define DD 128
#define KIN 256
#define NE 600000
#define LN_EPS 1e-5f
#define CHUNK 64

// ---------------- scratch ----------------
__device__ __align__(16) float g_x[(size_t)NN * DD];
__device__ __align__(16) float g_y[(size_t)NN * DD];
__device__ __align__(16) float g_uout[(size_t)NN * DD];
__device__ __align__(16) float g_uin[(size_t)NN * DD];
__device__ float g_invs[NN];
__device__ float g_invt[NN];

__device__ int g_cnt_t[NN], g_cnt_s[NN];
__device__ int g_off_t[NN], g_off_s[NN];
__device__ int g_woff_t[NN], g_woff_s[NN];
__device__ int g_list_t[NE], g_list_s[NE];
__device__ int g_bsum[512];

// ---------------- helpers ----------------
__device__ __forceinline__ void fma2(unsigned long long& d, unsigned long long a,
                                     unsigned long long b) {
    asm("fma.rn.f32x2 %0, %1, %2, %0;" : "+l"(d) : "l"(a), "l"(b));
}
__device__ __forceinline__ float2 unpack2(unsigned long long v) {
    float2 r;
    r.x = __uint_as_float((unsigned int)v);
    r.y = __uint_as_float((unsigned int)(v >> 32));
    return r;
}
__device__ __forceinline__ uint32_t rna_tf32(float x) {
    uint32_t r;
    asm("cvt.rna.tf32.f32 %0, %1;" : "=r"(r) : "f"(x));
    return r;
}
// warp-level tf32 mma: D(16x8) += A(16x8) * B(8x8)
__device__ __forceinline__ void mma_tf32(float* d, const uint32_t* a, const uint32_t* b) {
    asm volatile(
        "mma.sync.aligned.m16n8k8.row.col.f32.tf32.tf32.f32 "
        "{%0,%1,%2,%3}, {%4,%5,%6,%7}, {%8,%9}, {%0,%1,%2,%3};"
        : "+f"(d[0]), "+f"(d[1]), "+f"(d[2]), "+f"(d[3])
        : "r"(a[0]), "r"(a[1]), "r"(a[2]), "r"(a[3]), "r"(b[0]), "r"(b[1]));
}

// ================= CSR build =================
__global__ void k_csr_zero() {
    int i = blockIdx.x * blockDim.x + threadIdx.x;
    if (i < NN) { g_cnt_t[i] = 0; g_cnt_s[i] = 0; }
}
__global__ void k_hist(const int* __restrict__ s, const int* __restrict__ t) {
    int e = blockIdx.x * blockDim.x + threadIdx.x;
    if (e < NE) {
        atomicAdd(&g_cnt_t[t[e]], 1);
        atomicAdd(&g_cnt_s[s[e]], 1);
    }
}
__global__ void __launch_bounds__(512) k_scan1() {
    __shared__ int sh[512];
    int i = blockIdx.x * 512 + threadIdx.x;
    int v = (i < NN) ? g_cnt_t[i] : 0;
    sh[threadIdx.x] = v;
    __syncthreads();
    for (int o = 256; o; o >>= 1) {
        if (threadIdx.x < o) sh[threadIdx.x] += sh[threadIdx.x + o];
        __syncthreads();
    }
    if (threadIdx.x == 0) g_bsum[blockIdx.x] = sh[0];
    __syncthreads();
    int w = (i < NN) ? g_cnt_s[i] : 0;
    sh[threadIdx.x] = w;
    __syncthreads();
    for (int o = 256; o; o >>= 1) {
        if (threadIdx.x < o) sh[threadIdx.x] += sh[threadIdx.x + o];
        __syncthreads();
    }
    if (threadIdx.x == 0) g_bsum[256 + blockIdx.x] = sh[0];
}
__global__ void __launch_bounds__(256) k_scan2(int nblk) {
    __shared__ int st[256], ss[256];
    int b = threadIdx.x;
    int vt = (b < nblk) ? g_bsum[b] : 0;
    int vs = (b < nblk) ? g_bsum[256 + b] : 0;
    st[b] = vt; ss[b] = vs;
    __syncthreads();
    for (int o = 1; o < 256; o <<= 1) {
        int at = (b >= o) ? st[b - o] : 0;
        int as = (b >= o) ? ss[b - o] : 0;
        __syncthreads();
        st[b] += at; ss[b] += as;
        __syncthreads();
    }
    if (b < nblk) {
        g_bsum[b] = st[b] - vt;
        g_bsum[256 + b] = ss[b] - vs;
    }
}
__global__ void __launch_bounds__(512) k_scan3() {
    __shared__ int st[512], ss[512];
    int tid = threadIdx.x;
    int i = blockIdx.x * 512 + tid;
    int vt = (i < NN) ? g_cnt_t[i] : 0;
    int vs = (i < NN) ? g_cnt_s[i] : 0;
    st[tid] = vt; ss[tid] = vs;
    __syncthreads();
    for (int o = 1; o < 512; o <<= 1) {
        int at = (tid >= o) ? st[tid - o] : 0;
        int as = (tid >= o) ? ss[tid - o] : 0;
        __syncthreads();
        st[tid] += at; ss[tid] += as;
        __syncthreads();
    }
    if (i < NN) {
        int et = st[tid] - vt + g_bsum[blockIdx.x];
        int es = ss[tid] - vs + g_bsum[256 + blockIdx.x];
        g_off_t[i] = et; g_woff_t[i] = et;
        g_off_s[i] = es; g_woff_s[i] = es;
        g_invt[i] = vt > 0 ? rsqrtf((float)vt) : 0.f;
        g_invs[i] = vs > 0 ? rsqrtf((float)vs) : 0.f;
    }
}
__global__ void k_fill(const int* __restrict__ s, const int* __restrict__ r,
                       const int* __restrict__ t) {
    int e = blockIdx.x * blockDim.x + threadIdx.x;
    if (e < NE) {
        int si = s[e], ri = r[e], ti = t[e];
        int pt = atomicAdd(&g_woff_t[ti], 1);
        g_list_t[pt] = si | (ri << 17);
        int ps = atomicAdd(&g_woff_s[si], 1);
        g_list_s[ps] = ti | (ri << 17);
    }
}
__global__ void k_copyB(const float* __restrict__ embB) {
    int n = NA * DD / 4;
    float4* dst = (float4*)(g_x + (size_t)NA * DD);
    const float4* src = (const float4*)embB;
    for (int i = blockIdx.x * blockDim.x + threadIdx.x; i < n;
         i += gridDim.x * blockDim.x) {
        dst[i] = src[i];
    }
}

// ================= gather-aggregate =================
__global__ void __launch_bounds__(256) k_gather(int layer, const float* __restrict__ rel) {
    __shared__ float srel[32 * DD];
    int tid = threadIdx.x;
    for (int i = tid; i < 32 * DD; i += 256) srel[i] = rel[i];
    __syncthreads();

    int lane = tid & 31;
    int warp = tid >> 5;
    const float4* x4 = (const float4*)(layer ? g_y : g_x);

#pragma unroll
    for (int nd = 0; nd < 4; nd++) {
        int n = blockIdx.x * 32 + warp * 4 + nd;
        {
            float4 a0 = make_float4(0.f, 0.f, 0.f, 0.f);
            float4 a1 = make_float4(0.f, 0.f, 0.f, 0.f);
            int beg = g_off_t[n];
            int cnt = g_cnt_t[n];
            int j = 0;
            for (; j + 2 <= cnt; j += 2) {
                int v0 = __ldg(g_list_t + beg + j);
                int v1 = __ldg(g_list_t + beg + j + 1);
                int s0 = v0 & 131071, r0 = v0 >> 17;
                int s1 = v1 & 131071, r1 = v1 >> 17;
                float w0 = __ldg(g_invs + s0);
                float w1 = __ldg(g_invs + s1);
                float4 x0 = __ldg(x4 + (size_t)s0 * 32 + lane);
                float4 x1 = __ldg(x4 + (size_t)s1 * 32 + lane);
                float4 q0 = *(const float4*)&srel[r0 * DD + lane * 4];
                float4 q1 = *(const float4*)&srel[r1 * DD + lane * 4];
                a0.x = fmaf(w0, x0.x - q0.x, a0.x);
                a0.y = fmaf(w0, x0.y - q0.y, a0.y);
                a0.z = fmaf(w0, x0.z - q0.z, a0.z);
                a0.w = fmaf(w0, x0.w - q0.w, a0.w);
                a1.x = fmaf(w1, x1.x - q1.x, a1.x);
                a1.y = fmaf(w1, x1.y - q1.y, a1.y);
                a1.z = fmaf(w1, x1.z - q1.z, a1.z);
                a1.w = fmaf(w1, x1.w - q1.w, a1.w);
            }
            if (j < cnt) {
                int v0 = __ldg(g_list_t + beg + j);
                int s0 = v0 & 131071, r0 = v0 >> 17;
                float w0 = __ldg(g_invs + s0);
                float4 x0 = __ldg(x4 + (size_t)s0 * 32 + lane);
                float4 q0 = *(const float4*)&srel[r0 * DD + lane * 4];
                a0.x = fmaf(w0, x0.x - q0.x, a0.x);
                a0.y = fmaf(w0, x0.y - q0.y, a0.y);
                a0.z = fmaf(w0, x0.z - q0.z, a0.z);
                a0.w = fmaf(w0, x0.w - q0.w, a0.w);
            }
            float sc = g_invt[n];
            ((float4*)g_uout)[(size_t)n * 32 + lane] =
                make_float4((a0.x + a1.x) * sc, (a0.y + a1.y) * sc,
                            (a0.z + a1.z) * sc, (a0.w + a1.w) * sc);
        }
        {
            float4 a0 = make_float4(0.f, 0.f, 0.f, 0.f);
            float4 a1 = make_float4(0.f, 0.f, 0.f, 0.f);
            int beg = g_off_s[n];
            int cnt = g_cnt_s[n];
            int j = 0;
            for (; j + 2 <= cnt; j += 2) {
                int v0 = __ldg(g_list_s + beg + j);
                int v1 = __ldg(g_list_s + beg + j + 1);
                int t0 = v0 & 131071, r0 = v0 >> 17;
                int t1 = v1 & 131071, r1 = v1 >> 17;
                float w0 = __ldg(g_invt + t0);
                float w1 = __ldg(g_invt + t1);
                float4 x0 = __ldg(x4 + (size_t)t0 * 32 + lane);
                float4 x1 = __ldg(x4 + (size_t)t1 * 32 + lane);
                float4 q0 = *(const float4*)&srel[r0 * DD + lane * 4];
                float4 q1 = *(const float4*)&srel[r1 * DD + lane * 4];
                a0.x = fmaf(w0, x0.x - q0.x, a0.x);
                a0.y = fmaf(w0, x0.y - q0.y, a0.y);
                a0.z = fmaf(w0, x0.z - q0.z, a0.z);
                a0.w = fmaf(w0, x0.w - q0.w, a0.w);
                a1.x = fmaf(w1, x1.x - q1.x, a1.x);
                a1.y = fmaf(w1, x1.y - q1.y, a1.y);
                a1.z = fmaf(w1, x1.z - q1.z, a1.z);
                a1.w = fmaf(w1, x1.w - q1.w, a1.w);
            }
            if (j < cnt) {
                int v0 = __ldg(g_list_s + beg + j);
                int t0 = v0 & 131071, r0 = v0 >> 17;
                float w0 = __ldg(g_invt + t0);
                float4 x0 = __ldg(x4 + (size_t)t0 * 32 + lane);
                float4 q0 = *(const float4*)&srel[r0 * DD + lane * 4];
                a0.x = fmaf(w0, x0.x - q0.x, a0.x);
                a0.y = fmaf(w0, x0.y - q0.y, a0.y);
                a0.z = fmaf(w0, x0.z - q0.z, a0.z);
                a0.w = fmaf(w0, x0.w - q0.w, a0.w);
            }
            float sc = g_invs[n];
            ((float4*)g_uin)[(size_t)n * 32 + lane] =
                make_float4((a0.x + a1.x) * sc, (a0.y + a1.y) * sc,
                            (a0.z + a1.z) * sc, (a0.w + a1.w) * sc);
        }
    }
}

// ================= MLP (FFMA2) =================
__global__ void __launch_bounds__(256, 3) k_mlp(const float* __restrict__ X,
                                                const float* __restrict__ W,
                                                const float* __restrict__ b) {
    extern __shared__ float sm[];
    float* sw = sm;
    unsigned long long* su = (unsigned long long*)(sm + CHUNK * DD);

    int tid = threadIdx.x;
    int tx = tid & 31, ty = tid >> 5;
    int c0 = tx * 4, r0 = ty * 8;
    int row0 = blockIdx.x * 64;

    unsigned long long acc[8][2];
#pragma unroll
    for (int i = 0; i < 8; i++) { acc[i][0] = 0ull; acc[i][1] = 0ull; }

    for (int kc = 0; kc < KIN / CHUNK; kc++) {
        __syncthreads();
        for (int idx = tid; idx < DD * CHUNK; idx += 256) {
            int o = idx >> 6, k = idx & 63;
            int j = o >> 2, sub = o & 3;
            sw[k * DD + (((j ^ (k & 31)) << 2) + sub)] = W[o * KIN + kc * CHUNK + k];
        }
        for (int idx = tid; idx < 64 * (CHUNK / 4); idx += 256) {
            int r = idx >> 4, c4 = idx & 15;
            int row = row0 + r;
            float4 v = make_float4(0.f, 0.f, 0.f, 0.f);
            if (row < NA) v = ((const float4*)X)[(size_t)row * (KIN / 4) + kc * 16 + c4];
            float2* sp = (float2*)&su[r * CHUNK + c4 * 4];
            sp[0] = make_float2(v.x, v.x);
            sp[1] = make_float2(v.y, v.y);
            sp[2] = make_float2(v.z, v.z);
            sp[3] = make_float2(v.w, v.w);
        }
        __syncthreads();

#pragma unroll 4
        for (int k = 0; k < CHUNK; k += 2) {
            ulonglong2 wa = *(const ulonglong2*)&sw[k * DD + ((tx ^ (k & 31)) << 2)];
            ulonglong2 wb = *(const ulonglong2*)&sw[(k + 1) * DD + ((tx ^ ((k + 1) & 31)) << 2)];
#pragma unroll
            for (int i = 0; i < 8; i++) {
                ulonglong2 u = *(const ulonglong2*)&su[(r0 + i) * CHUNK + k];
                fma2(acc[i][0], u.x, wa.x);
                fma2(acc[i][1], u.x, wa.y);
                fma2(acc[i][0], u.y, wb.x);
                fma2(acc[i][1], u.y, wb.y);
            }
        }
    }

    float4 bb = __ldg((const float4*)b + tx);
#pragma unroll
    for (int i = 0; i < 8; i++) {
        int row = row0 + r0 + i;
        if (row < NA) {
            float2 p0 = unpack2(acc[i][0]);
            float2 p1 = unpack2(acc[i][1]);
            *(float4*)&g_x[(size_t)row * DD + c0] =
                make_float4(p0.x + bb.x, p0.y + bb.y, p1.x + bb.z, p1.y + bb.w);
        }
    }
}

// ================= fused conv via warp-level tf32 mma.sync =================
// CTA: 512 thr / 16 warps, 256 nodes x 128 out-cols.
// Warp (wm, wn) in 4x4 grid owns 64x32 = 4x4 m16n8k8 tiles.
// Per matrix m: D += rna(A_m) * (rna(B) + rna(B - rna(B)))  [split-B 2-pass]
// smem: A_frag [kt16][mt16][lane32][4] = 32768 f (128KB)
//       B_frag [kt16][nt16][lane32][2] = 16384 f (64KB)
//       params 384 f;  epilogue reuses A/B region (256*133 f)
#define SM_BOFF 32768
#define SM_POFF 49152
#define SMEM_MMA ((49152 + 384) * 4)
#define EPS_T 133

__global__ void __launch_bounds__(512) k_fused_mma(
    int layer, const float* __restrict__ Wout, const float* __restrict__ Win,
    const float* __restrict__ Wloop, const float* __restrict__ loop_rel,
    const float* __restrict__ bias, const float* __restrict__ lng,
    const float* __restrict__ lnb, float* __restrict__ dout) {
    extern __shared__ float sm[];
    uint32_t* Au = (uint32_t*)sm;
    uint32_t* Bu = (uint32_t*)(sm + SM_BOFF);
    float* spar = sm + SM_POFF;

    int tid = threadIdx.x;
    int lane = tid & 31;
    int wid = tid >> 5;
    int wm = wid & 3, wn = wid >> 2;
    int row0 = blockIdx.x * 256;

    const float4* x4 = (const float4*)(layer ? g_y : g_x);
    float* out = layer ? dout : g_y;

    if (tid < 128) {
        spar[tid] = bias[tid];
        spar[128 + tid] = lng[tid];
        spar[256 + tid] = lnb[tid];
    }

    float acc[4][4][4];
#pragma unroll
    for (int i = 0; i < 4; i++)
#pragma unroll
        for (int j = 0; j < 4; j++)
#pragma unroll
            for (int c = 0; c < 4; c++) acc[i][j][c] = 0.f;

    for (int m = 0; m < 3; m++) {
        const float4* W4 = (const float4*)((m == 0) ? Wout : (m == 1) ? Win : Wloop);
        __syncthreads();
        // ---- stage A_m (fragment order, rna tf32) ----
        for (int idx = tid; idx < 256 * 32; idx += 512) {
            int r = idx >> 5, c4 = idx & 31;
            int node = row0 + r;
            float4 v = make_float4(0.f, 0.f, 0.f, 0.f);
            if (node < NN) {
                if (m == 0) v = ((const float4*)g_uout)[(size_t)node * 32 + c4];
                else if (m == 1) v = ((const float4*)g_uin)[(size_t)node * 32 + c4];
                else {
                    float4 u = x4[(size_t)node * 32 + c4];
                    float4 lr = __ldg((const float4*)loop_rel + c4);
                    v = make_float4(u.x - lr.x, u.y - lr.y, u.z - lr.z, u.w - lr.w);
                }
            }
            int kt = c4 >> 1;
            int mt = r >> 4;
            int jb = (c4 & 1) * 2 + ((r & 15) >> 3);
            uint32_t base = (uint32_t)(((kt * 16 + mt) * 32 + (r & 7) * 4) * 4 + jb);
            Au[base + 0] = rna_tf32(v.x);
            Au[base + 4] = rna_tf32(v.y);
            Au[base + 8] = rna_tf32(v.z);
            Au[base + 12] = rna_tf32(v.w);
        }
        // ---- stage B_m hi ----
        for (int idx = tid; idx < 128 * 32; idx += 512) {
            int o = idx >> 5, c4 = idx & 31;
            float4 w = __ldg(W4 + o * 32 + c4);
            int kt = c4 >> 1, j = c4 & 1;
            int nt = o >> 3;
            uint32_t base = (uint32_t)(((kt * 16 + nt) * 32 + (o & 7) * 4) * 2 + j);
            Bu[base + 0] = rna_tf32(w.x);
            Bu[base + 2] = rna_tf32(w.y);
            Bu[base + 4] = rna_tf32(w.z);
            Bu[base + 6] = rna_tf32(w.w);
        }
        __syncthreads();

        for (int pass = 0; pass < 2; pass++) {
            // ---- mma pass over K ----
#pragma unroll 2
            for (int kt = 0; kt < 16; kt++) {
                uint32_t a[4][4], b[4][2];
#pragma unroll
                for (int i = 0; i < 4; i++) {
                    uint4 t = *(const uint4*)&Au[((kt * 16 + wm * 4 + i) * 32 + lane) * 4];
                    a[i][0] = t.x; a[i][1] = t.y; a[i][2] = t.z; a[i][3] = t.w;
                }
#pragma unroll
                for (int i = 0; i < 4; i++) {
                    uint2 t = *(const uint2*)&Bu[((kt * 16 + wn * 4 + i) * 32 + lane) * 2];
                    b[i][0] = t.x; b[i][1] = t.y;
                }
#pragma unroll
                for (int i = 0; i < 4; i++)
#pragma unroll
                    for (int j = 0; j < 4; j++) mma_tf32(acc[i][j], a[i], b[j]);
            }

            if (pass == 0) {
                // ---- restage B_m lo ----
                __syncthreads();
                for (int idx = tid; idx < 128 * 32; idx += 512) {
                    int o = idx >> 5, c4 = idx & 31;
                    float4 w = __ldg(W4 + o * 32 + c4);
                    int kt = c4 >> 1, j = c4 & 1;
                    int nt = o >> 3;
                    uint32_t base = (uint32_t)(((kt * 16 + nt) * 32 + (o & 7) * 4) * 2 + j);
                    Bu[base + 0] = rna_tf32(w.x - __uint_as_float(rna_tf32(w.x)));
                    Bu[base + 2] = rna_tf32(w.y - __uint_as_float(rna_tf32(w.y)));
                    Bu[base + 4] = rna_tf32(w.z - __uint_as_float(rna_tf32(w.z)));
                    Bu[base + 6] = rna_tf32(w.w - __uint_as_float(rna_tf32(w.w)));
                }
                __syncthreads();
            }
        }
    }

    // ---- epilogue: acc -> smem, per-row LN, coalesced store ----
    __syncthreads();
    float* epi = sm;   // reuse A/B region (256*133 = 34048 floats < 49152)
#pragma unroll
    for (int i = 0; i < 4; i++) {
#pragma unroll
        for (int j = 0; j < 4; j++) {
            int row = wm * 64 + i * 16 + (lane >> 2);
            int col = wn * 32 + j * 8 + (lane & 3) * 2;
            epi[row * EPS_T + col] = acc[i][j][0];
            epi[row * EPS_T + col + 1] = acc[i][j][1];
            epi[(row + 8) * EPS_T + col] = acc[i][j][2];
            epi[(row + 8) * EPS_T + col + 1] = acc[i][j][3];
        }
    }
    __syncthreads();

    const float inv3 = 1.f / 3.f;
    const float invD = 1.f / 128.f;
    if (tid < 256) {
        int r = tid;
        float s1 = 0.f, s2 = 0.f;
#pragma unroll 4
        for (int c = 0; c < 128; c++) {
            float v = epi[r * EPS_T + c] * inv3 + spar[c];
            if (layer == 0) v = fmaxf(v, 0.f);
            epi[r * EPS_T + c] = v;
            s1 += v;
            s2 += v * v;
        }
        float mu = s1 * invD;
        float var = fmaxf(s2 * invD - mu * mu, 0.f);
        float rstd = rsqrtf(var + LN_EPS);
#pragma unroll 4
        for (int c = 0; c < 128; c++) {
            float v = epi[r * EPS_T + c];
            epi[r * EPS_T + c] = (v - mu) * rstd * spar[128 + c] + spar[256 + c];
        }
    }
    __syncthreads();

    for (int idx = tid; idx < 256 * 32; idx += 512) {
        int r = idx >> 5, c4 = idx & 31;
        int node = row0 + r;
        if (node < NN) {
            const float* p = &epi[r * EPS_T + c4 * 4];
            ((float4*)out)[(size_t)node * 32 + c4] =
                make_float4(p[0], p[1], p[2], p[3]);
        }
    }
}

// ================= launch =================
extern "C" void kernel_launch(void* const* d_in, const int* in_sizes, int n_in,
                              void* d_out, int out_size) {
    const float* x_typeA = (const float*)d_in[0];
    const float* W_mlp   = (const float*)d_in[1];
    const float* b_mlp   = (const float*)d_in[2];
    const float* emb_B   = (const float*)d_in[3];
    const float* rel0    = (const float*)d_in[4];
    const float* lrel0   = (const float*)d_in[5];
    const float* wloop0  = (const float*)d_in[6];
    const float* win0    = (const float*)d_in[7];
    const float* wout0   = (const float*)d_in[8];
    const float* bias0   = (const float*)d_in[9];
    const float* lng0    = (const float*)d_in[10];
    const float* lnb0    = (const float*)d_in[11];
    const float* rel1    = (const float*)d_in[12];
    const float* lrel1   = (const float*)d_in[13];
    const float* wloop1  = (const float*)d_in[14];
    const float* win1    = (const float*)d_in[15];
    const float* wout1   = (const float*)d_in[16];
    const float* bias1   = (const float*)d_in[17];
    const float* lng1    = (const float*)d_in[18];
    const float* lnb1    = (const float*)d_in[19];
    const int*   esrc    = (const int*)d_in[20];
    const int*   erel    = (const int*)d_in[21];
    const int*   edst    = (const int*)d_in[22];
    float* out = (float*)d_out;

    const int smem_mlp = CHUNK * DD * 4 + 64 * CHUNK * 8;   // 65536
    cudaFuncSetAttribute(k_mlp, cudaFuncAttributeMaxDynamicSharedMemorySize, smem_mlp);
    cudaFuncSetAttribute(k_fused_mma, cudaFuncAttributeMaxDynamicSharedMemorySize, SMEM_MMA);

    const int nScanBlk = (NN + 511) / 512;   // 196
    const int nMmaBlk = (NN + 255) / 256;    // 391

    k_csr_zero<<<(NN + 255) / 256, 256>>>();
    k_hist<<<(NE + 255) / 256, 256>>>(esrc, edst);
    k_scan1<<<nScanBlk, 512>>>();
    k_scan2<<<1, 256>>>(nScanBlk);
    k_scan3<<<nScanBlk, 512>>>();

    k_mlp<<<(NA + 63) / 64, 256, smem_mlp>>>(x_typeA, W_mlp, b_mlp);
    k_fill<<<(NE + 255) / 256, 256>>>(esrc, erel, edst);
    k_copyB<<<2048, 256>>>(emb_B);

    k_gather<<<NN / 32, 256>>>(0, rel0);
    k_fused_mma<<<nMmaBlk, 512, SMEM_MMA>>>(0, wout0, win0, wloop0, lrel0,
                                            bias0, lng0, lnb0, out);
    k_gather<<<NN / 32, 256>>>(1, rel1);
    k_fused_mma<<<nMmaBlk, 512, SMEM_MMA>>>(1, wout1, win1, wloop1, lrel1,
                                            bias1, lng1, lnb1, out);
}

// round 6
// speedup vs baseline: 1.9871x; 1.3228x over previous
#include <cuda_runtime.h>
#include <cstdint>

#define NN 100000
#define NA 50000
#define DD 128
#define KIN 256
#define NE 600000
#define LN_EPS 1e-5f
#define CHUNK 64

// ---------------- scratch ----------------
__device__ __align__(16) float g_x[(size_t)NN * DD];
__device__ __align__(16) float g_y[(size_t)NN * DD];
__device__ __align__(16) float g_uout[(size_t)NN * DD];
__device__ __align__(16) float g_uin[(size_t)NN * DD];
__device__ float g_invs[NN];
__device__ float g_invt[NN];

__device__ int g_cnt_t[NN], g_cnt_s[NN];
__device__ int g_off_t[NN], g_off_s[NN];
__device__ int g_woff_t[NN], g_woff_s[NN];
__device__ int g_list_t[NE], g_list_s[NE];
__device__ int g_bsum[512];

// B weights pre-converted to tf32 fragment layout:
// [mi(6)][pass(2)][kt(16)][nt(16)][lane(32)][reg(2)]
__device__ __align__(16) uint32_t g_bfrag[6 * 2 * 16 * 16 * 32 * 2];

// ---------------- helpers ----------------
__device__ __forceinline__ void fma2(unsigned long long& d, unsigned long long a,
                                     unsigned long long b) {
    asm("fma.rn.f32x2 %0, %1, %2, %0;" : "+l"(d) : "l"(a), "l"(b));
}
__device__ __forceinline__ float2 unpack2(unsigned long long v) {
    float2 r;
    r.x = __uint_as_float((unsigned int)v);
    r.y = __uint_as_float((unsigned int)(v >> 32));
    return r;
}
__device__ __forceinline__ uint32_t rna_tf32(float x) {
    uint32_t r;
    asm("cvt.rna.tf32.f32 %0, %1;" : "=r"(r) : "f"(x));
    return r;
}
__device__ __forceinline__ void mma_tf32(float* d, const uint32_t* a, const uint32_t* b) {
    asm volatile(
        "mma.sync.aligned.m16n8k8.row.col.f32.tf32.tf32.f32 "
        "{%0,%1,%2,%3}, {%4,%5,%6,%7}, {%8,%9}, {%0,%1,%2,%3};"
        : "+f"(d[0]), "+f"(d[1]), "+f"(d[2]), "+f"(d[3])
        : "r"(a[0]), "r"(a[1]), "r"(a[2]), "r"(a[3]), "r"(b[0]), "r"(b[1]));
}

// ================= CSR build =================
__global__ void k_csr_zero() {
    int i = blockIdx.x * blockDim.x + threadIdx.x;
    if (i < NN) { g_cnt_t[i] = 0; g_cnt_s[i] = 0; }
}
__global__ void k_hist(const int* __restrict__ s, const int* __restrict__ t) {
    int e = blockIdx.x * blockDim.x + threadIdx.x;
    if (e < NE) {
        atomicAdd(&g_cnt_t[t[e]], 1);
        atomicAdd(&g_cnt_s[s[e]], 1);
    }
}
__global__ void __launch_bounds__(512) k_scan1() {
    __shared__ int sh[512];
    int i = blockIdx.x * 512 + threadIdx.x;
    int v = (i < NN) ? g_cnt_t[i] : 0;
    sh[threadIdx.x] = v;
    __syncthreads();
    for (int o = 256; o; o >>= 1) {
        if (threadIdx.x < o) sh[threadIdx.x] += sh[threadIdx.x + o];
        __syncthreads();
    }
    if (threadIdx.x == 0) g_bsum[blockIdx.x] = sh[0];
    __syncthreads();
    int w = (i < NN) ? g_cnt_s[i] : 0;
    sh[threadIdx.x] = w;
    __syncthreads();
    for (int o = 256; o; o >>= 1) {
        if (threadIdx.x < o) sh[threadIdx.x] += sh[threadIdx.x + o];
        __syncthreads();
    }
    if (threadIdx.x == 0) g_bsum[256 + blockIdx.x] = sh[0];
}
__global__ void __launch_bounds__(256) k_scan2(int nblk) {
    __shared__ int st[256], ss[256];
    int b = threadIdx.x;
    int vt = (b < nblk) ? g_bsum[b] : 0;
    int vs = (b < nblk) ? g_bsum[256 + b] : 0;
    st[b] = vt; ss[b] = vs;
    __syncthreads();
    for (int o = 1; o < 256; o <<= 1) {
        int at = (b >= o) ? st[b - o] : 0;
        int as = (b >= o) ? ss[b - o] : 0;
        __syncthreads();
        st[b] += at; ss[b] += as;
        __syncthreads();
    }
    if (b < nblk) {
        g_bsum[b] = st[b] - vt;
        g_bsum[256 + b] = ss[b] - vs;
    }
}
__global__ void __launch_bounds__(512) k_scan3() {
    __shared__ int st[512], ss[512];
    int tid = threadIdx.x;
    int i = blockIdx.x * 512 + tid;
    int vt = (i < NN) ? g_cnt_t[i] : 0;
    int vs = (i < NN) ? g_cnt_s[i] : 0;
    st[tid] = vt; ss[tid] = vs;
    __syncthreads();
    for (int o = 1; o < 512; o <<= 1) {
        int at = (tid >= o) ? st[tid - o] : 0;
        int as = (tid >= o) ? ss[tid - o] : 0;
        __syncthreads();
        st[tid] += at; ss[tid] += as;
        __syncthreads();
    }
    if (i < NN) {
        int et = st[tid] - vt + g_bsum[blockIdx.x];
        int es = ss[tid] - vs + g_bsum[256 + blockIdx.x];
        g_off_t[i] = et; g_woff_t[i] = et;
        g_off_s[i] = es; g_woff_s[i] = es;
        g_invt[i] = vt > 0 ? rsqrtf((float)vt) : 0.f;
        g_invs[i] = vs > 0 ? rsqrtf((float)vs) : 0.f;
    }
}
__global__ void k_fill(const int* __restrict__ s, const int* __restrict__ r,
                       const int* __restrict__ t) {
    int e = blockIdx.x * blockDim.x + threadIdx.x;
    if (e < NE) {
        int si = s[e], ri = r[e], ti = t[e];
        int pt = atomicAdd(&g_woff_t[ti], 1);
        g_list_t[pt] = si | (ri << 17);
        int ps = atomicAdd(&g_woff_s[si], 1);
        g_list_s[ps] = ti | (ri << 17);
    }
}
__global__ void k_copyB(const float* __restrict__ embB) {
    int n = NA * DD / 4;
    float4* dst = (float4*)(g_x + (size_t)NA * DD);
    const float4* src = (const float4*)embB;
    for (int i = blockIdx.x * blockDim.x + threadIdx.x; i < n;
         i += gridDim.x * blockDim.x) {
        dst[i] = src[i];
    }
}

// ================= weight pre-conversion to fragment tf32 =================
// flat index: ((((mi*2+pass)*16 + kt)*16 + nt)*32 + lane)*2 + reg
__global__ void k_convB(const float* __restrict__ w0, const float* __restrict__ w1,
                        const float* __restrict__ w2, const float* __restrict__ w3,
                        const float* __restrict__ w4, const float* __restrict__ w5) {
    int idx = blockIdx.x * 256 + threadIdx.x;
    if (idx >= 6 * 4096) return;
    int mi = idx >> 12;
    int e = idx & 4095;
    int o = e >> 5, c4 = e & 31;
    const float* W = (mi == 0) ? w0 : (mi == 1) ? w1 : (mi == 2) ? w2
                   : (mi == 3) ? w3 : (mi == 4) ? w4 : w5;
    float4 w = __ldg((const float4*)W + o * 32 + c4);
    int kt = c4 >> 1, j = c4 & 1, nt = o >> 3;
    float wv[4] = {w.x, w.y, w.z, w.w};
#pragma unroll
    for (int c = 0; c < 4; c++) {
        int lane = (o & 7) * 4 + c;
        uint32_t hi = rna_tf32(wv[c]);
        uint32_t lo = rna_tf32(wv[c] - __uint_as_float(hi));
        uint32_t fh = ((((mi * 2 + 0) * 16 + kt) * 16 + nt) * 32 + lane) * 2 + j;
        uint32_t fl = ((((mi * 2 + 1) * 16 + kt) * 16 + nt) * 32 + lane) * 2 + j;
        g_bfrag[fh] = hi;
        g_bfrag[fl] = lo;
    }
}

// ================= gather-aggregate =================
__global__ void __launch_bounds__(256) k_gather(int layer, const float* __restrict__ rel) {
    __shared__ float srel[32 * DD];
    int tid = threadIdx.x;
    for (int i = tid; i < 32 * DD; i += 256) srel[i] = rel[i];
    __syncthreads();

    int lane = tid & 31;
    int warp = tid >> 5;
    const float4* x4 = (const float4*)(layer ? g_y : g_x);

#pragma unroll
    for (int nd = 0; nd < 4; nd++) {
        int n = blockIdx.x * 32 + warp * 4 + nd;
        {
            float4 a0 = make_float4(0.f, 0.f, 0.f, 0.f);
            float4 a1 = make_float4(0.f, 0.f, 0.f, 0.f);
            int beg = g_off_t[n];
            int cnt = g_cnt_t[n];
            int j = 0;
            for (; j + 2 <= cnt; j += 2) {
                int v0 = __ldg(g_list_t + beg + j);
                int v1 = __ldg(g_list_t + beg + j + 1);
                int s0 = v0 & 131071, r0 = v0 >> 17;
                int s1 = v1 & 131071, r1 = v1 >> 17;
                float w0 = __ldg(g_invs + s0);
                float w1 = __ldg(g_invs + s1);
                float4 x0 = __ldg(x4 + (size_t)s0 * 32 + lane);
                float4 x1 = __ldg(x4 + (size_t)s1 * 32 + lane);
                float4 q0 = *(const float4*)&srel[r0 * DD + lane * 4];
                float4 q1 = *(const float4*)&srel[r1 * DD + lane * 4];
                a0.x = fmaf(w0, x0.x - q0.x, a0.x);
                a0.y = fmaf(w0, x0.y - q0.y, a0.y);
                a0.z = fmaf(w0, x0.z - q0.z, a0.z);
                a0.w = fmaf(w0, x0.w - q0.w, a0.w);
                a1.x = fmaf(w1, x1.x - q1.x, a1.x);
                a1.y = fmaf(w1, x1.y - q1.y, a1.y);
                a1.z = fmaf(w1, x1.z - q1.z, a1.z);
                a1.w = fmaf(w1, x1.w - q1.w, a1.w);
            }
            if (j < cnt) {
                int v0 = __ldg(g_list_t + beg + j);
                int s0 = v0 & 131071, r0 = v0 >> 17;
                float w0 = __ldg(g_invs + s0);
                float4 x0 = __ldg(x4 + (size_t)s0 * 32 + lane);
                float4 q0 = *(const float4*)&srel[r0 * DD + lane * 4];
                a0.x = fmaf(w0, x0.x - q0.x, a0.x);
                a0.y = fmaf(w0, x0.y - q0.y, a0.y);
                a0.z = fmaf(w0, x0.z - q0.z, a0.z);
                a0.w = fmaf(w0, x0.w - q0.w, a0.w);
            }
            float sc = g_invt[n];
            ((float4*)g_uout)[(size_t)n * 32 + lane] =
                make_float4((a0.x + a1.x) * sc, (a0.y + a1.y) * sc,
                            (a0.z + a1.z) * sc, (a0.w + a1.w) * sc);
        }
        {
            float4 a0 = make_float4(0.f, 0.f, 0.f, 0.f);
            float4 a1 = make_float4(0.f, 0.f, 0.f, 0.f);
            int beg = g_off_s[n];
            int cnt = g_cnt_s[n];
            int j = 0;
            for (; j + 2 <= cnt; j += 2) {
                int v0 = __ldg(g_list_s + beg + j);
                int v1 = __ldg(g_list_s + beg + j + 1);
                int t0 = v0 & 131071, r0 = v0 >> 17;
                int t1 = v1 & 131071, r1 = v1 >> 17;
                float w0 = __ldg(g_invt + t0);
                float w1 = __ldg(g_invt + t1);
                float4 x0 = __ldg(x4 + (size_t)t0 * 32 + lane);
                float4 x1 = __ldg(x4 + (size_t)t1 * 32 + lane);
                float4 q0 = *(const float4*)&srel[r0 * DD + lane * 4];
                float4 q1 = *(const float4*)&srel[r1 * DD + lane * 4];
                a0.x = fmaf(w0, x0.x - q0.x, a0.x);
                a0.y = fmaf(w0, x0.y - q0.y, a0.y);
                a0.z = fmaf(w0, x0.z - q0.z, a0.z);
                a0.w = fmaf(w0, x0.w - q0.w, a0.w);
                a1.x = fmaf(w1, x1.x - q1.x, a1.x);
                a1.y = fmaf(w1, x1.y - q1.y, a1.y);
                a1.z = fmaf(w1, x1.z - q1.z, a1.z);
                a1.w = fmaf(w1, x1.w - q1.w, a1.w);
            }
            if (j < cnt) {
                int v0 = __ldg(g_list_s + beg + j);
                int t0 = v0 & 131071, r0 = v0 >> 17;
                float w0 = __ldg(g_invt + t0);
                float4 x0 = __ldg(x4 + (size_t)t0 * 32 + lane);
                float4 q0 = *(const float4*)&srel[r0 * DD + lane * 4];
                a0.x = fmaf(w0, x0.x - q0.x, a0.x);
                a0.y = fmaf(w0, x0.y - q0.y, a0.y);
                a0.z = fmaf(w0, x0.z - q0.z, a0.z);
                a0.w = fmaf(w0, x0.w - q0.w, a0.w);
            }
            float sc = g_invs[n];
            ((float4*)g_uin)[(size_t)n * 32 + lane] =
                make_float4((a0.x + a1.x) * sc, (a0.y + a1.y) * sc,
                            (a0.z + a1.z) * sc, (a0.w + a1.w) * sc);
        }
    }
}

// ================= MLP (FFMA2) =================
__global__ void __launch_bounds__(256, 3) k_mlp(const float* __restrict__ X,
                                                const float* __restrict__ W,
                                                const float* __restrict__ b) {
    extern __shared__ float sm[];
    float* sw = sm;
    unsigned long long* su = (unsigned long long*)(sm + CHUNK * DD);

    int tid = threadIdx.x;
    int tx = tid & 31, ty = tid >> 5;
    int c0 = tx * 4, r0 = ty * 8;
    int row0 = blockIdx.x * 64;

    unsigned long long acc[8][2];
#pragma unroll
    for (int i = 0; i < 8; i++) { acc[i][0] = 0ull; acc[i][1] = 0ull; }

    for (int kc = 0; kc < KIN / CHUNK; kc++) {
        __syncthreads();
        for (int idx = tid; idx < DD * CHUNK; idx += 256) {
            int o = idx >> 6, k = idx & 63;
            int j = o >> 2, sub = o & 3;
            sw[k * DD + (((j ^ (k & 31)) << 2) + sub)] = W[o * KIN + kc * CHUNK + k];
        }
        for (int idx = tid; idx < 64 * (CHUNK / 4); idx += 256) {
            int r = idx >> 4, c4 = idx & 15;
            int row = row0 + r;
            float4 v = make_float4(0.f, 0.f, 0.f, 0.f);
            if (row < NA) v = ((const float4*)X)[(size_t)row * (KIN / 4) + kc * 16 + c4];
            float2* sp = (float2*)&su[r * CHUNK + c4 * 4];
            sp[0] = make_float2(v.x, v.x);
            sp[1] = make_float2(v.y, v.y);
            sp[2] = make_float2(v.z, v.z);
            sp[3] = make_float2(v.w, v.w);
        }
        __syncthreads();

#pragma unroll 4
        for (int k = 0; k < CHUNK; k += 2) {
            ulonglong2 wa = *(const ulonglong2*)&sw[k * DD + ((tx ^ (k & 31)) << 2)];
            ulonglong2 wb = *(const ulonglong2*)&sw[(k + 1) * DD + ((tx ^ ((k + 1) & 31)) << 2)];
#pragma unroll
            for (int i = 0; i < 8; i++) {
                ulonglong2 u = *(const ulonglong2*)&su[(r0 + i) * CHUNK + k];
                fma2(acc[i][0], u.x, wa.x);
                fma2(acc[i][1], u.x, wa.y);
                fma2(acc[i][0], u.y, wb.x);
                fma2(acc[i][1], u.y, wb.y);
            }
        }
    }

    float4 bb = __ldg((const float4*)b + tx);
#pragma unroll
    for (int i = 0; i < 8; i++) {
        int row = row0 + r0 + i;
        if (row < NA) {
            float2 p0 = unpack2(acc[i][0]);
            float2 p1 = unpack2(acc[i][1]);
            *(float4*)&g_x[(size_t)row * DD + c0] =
                make_float4(p0.x + bb.x, p0.y + bb.y, p1.x + bb.z, p1.y + bb.w);
        }
    }
}

// ================= fused conv via tf32 mma.sync (v2) =================
// CTA: 256 thr / 8 warps, 128 nodes x 128 cols; warp grid 2x4 (64x32 per warp).
// A staged in smem (fragment order, padded kt-stride 1028 -> 2-way STS).
// B read directly from g_bfrag (global, coalesced LDG).
#define PADKT 1028
#define SM_POFF 17024      /* epi = 128*133 floats */
#define SMF_MMA ((17024 + 384) * 4)
#define EPS_T 133

__global__ void __launch_bounds__(256, 2) k_fused_mma(
    int layer, const float* __restrict__ loop_rel,
    const float* __restrict__ bias, const float* __restrict__ lng,
    const float* __restrict__ lnb, float* __restrict__ dout) {
    extern __shared__ float sm[];
    uint32_t* Au = (uint32_t*)sm;
    float* spar = sm + SM_POFF;

    int tid = threadIdx.x;
    int lane = tid & 31;
    int wid = tid >> 5;
    int wm = wid & 1, wn = wid >> 1;
    int row0 = blockIdx.x * 128;

    const float4* x4 = (const float4*)(layer ? g_y : g_x);
    float* out = layer ? dout : g_y;

    if (tid < 128) {
        spar[tid] = bias[tid];
        spar[128 + tid] = lng[tid];
        spar[256 + tid] = lnb[tid];
    }

    float acc[4][4][4];
#pragma unroll
    for (int i = 0; i < 4; i++)
#pragma unroll
        for (int j = 0; j < 4; j++)
#pragma unroll
            for (int c = 0; c < 4; c++) acc[i][j][c] = 0.f;

    for (int m = 0; m < 3; m++) {
        __syncthreads();
        // ---- stage A_m (fragment order, rna tf32, padded kt stride) ----
        for (int idx = tid; idx < 128 * 32; idx += 256) {
            int r = idx >> 5, c4 = idx & 31;
            int node = row0 + r;
            float4 v = make_float4(0.f, 0.f, 0.f, 0.f);
            if (node < NN) {
                if (m == 0) v = ((const float4*)g_uout)[(size_t)node * 32 + c4];
                else if (m == 1) v = ((const float4*)g_uin)[(size_t)node * 32 + c4];
                else {
                    float4 u = x4[(size_t)node * 32 + c4];
                    float4 lr = __ldg((const float4*)loop_rel + c4);
                    v = make_float4(u.x - lr.x, u.y - lr.y, u.z - lr.z, u.w - lr.w);
                }
            }
            int kt = c4 >> 1;
            int mt = r >> 4;
            int jb = (c4 & 1) * 2 + ((r & 15) >> 3);
            uint32_t base = kt * PADKT + mt * 128 + (r & 7) * 16 + jb;
            Au[base + 0] = rna_tf32(v.x);
            Au[base + 4] = rna_tf32(v.y);
            Au[base + 8] = rna_tf32(v.z);
            Au[base + 12] = rna_tf32(v.w);
        }
        __syncthreads();

        int mi = layer * 3 + m;
#pragma unroll
        for (int pass = 0; pass < 2; pass++) {
            const uint32_t* bf = g_bfrag + (size_t)(mi * 2 + pass) * 16384;
#pragma unroll 4
            for (int kt = 0; kt < 16; kt++) {
                uint32_t a[4][4], b[4][2];
#pragma unroll
                for (int i = 0; i < 4; i++) {
                    uint4 t = *(const uint4*)&Au[kt * PADKT + (wm * 4 + i) * 128 + lane * 4];
                    a[i][0] = t.x; a[i][1] = t.y; a[i][2] = t.z; a[i][3] = t.w;
                }
#pragma unroll
                for (int i = 0; i < 4; i++) {
                    uint2 t = __ldg((const uint2*)&bf[((kt * 16 + wn * 4 + i) * 32 + lane) * 2]);
                    b[i][0] = t.x; b[i][1] = t.y;
                }
#pragma unroll
                for (int i = 0; i < 4; i++)
#pragma unroll
                    for (int j = 0; j < 4; j++) mma_tf32(acc[i][j], a[i], b[j]);
            }
        }
    }

    // ---- epilogue: acc -> smem, per-row LN, coalesced store ----
    __syncthreads();
    float* epi = sm;
#pragma unroll
    for (int i = 0; i < 4; i++) {
#pragma unroll
        for (int j = 0; j < 4; j++) {
            int row = wm * 64 + i * 16 + (lane >> 2);
            int col = wn * 32 + j * 8 + (lane & 3) * 2;
            epi[row * EPS_T + col] = acc[i][j][0];
            epi[row * EPS_T + col + 1] = acc[i][j][1];
            epi[(row + 8) * EPS_T + col] = acc[i][j][2];
            epi[(row + 8) * EPS_T + col + 1] = acc[i][j][3];
        }
    }
    __syncthreads();

    const float inv3 = 1.f / 3.f;
    const float invD = 1.f / 128.f;
    if (tid < 128) {
        int r = tid;
        float s1 = 0.f, s2 = 0.f;
#pragma unroll 4
        for (int c = 0; c < 128; c++) {
            float v = epi[r * EPS_T + c] * inv3 + spar[c];
            if (layer == 0) v = fmaxf(v, 0.f);
            epi[r * EPS_T + c] = v;
            s1 += v;
            s2 += v * v;
        }
        float mu = s1 * invD;
        float var = fmaxf(s2 * invD - mu * mu, 0.f);
        float rstd = rsqrtf(var + LN_EPS);
#pragma unroll 4
        for (int c = 0; c < 128; c++) {
            float v = epi[r * EPS_T + c];
            epi[r * EPS_T + c] = (v - mu) * rstd * spar[128 + c] + spar[256 + c];
        }
    }
    __syncthreads();

    for (int idx = tid; idx < 128 * 32; idx += 256) {
        int r = idx >> 5, c4 = idx & 31;
        int node = row0 + r;
        if (node < NN) {
            const float* p = &epi[r * EPS_T + c4 * 4];
            ((float4*)out)[(size_t)node * 32 + c4] =
                make_float4(p[0], p[1], p[2], p[3]);
        }
    }
}

// ================= launch =================
extern "C" void kernel_launch(void* const* d_in, const int* in_sizes, int n_in,
                              void* d_out, int out_size) {
    const float* x_typeA = (const float*)d_in[0];
    const float* W_mlp   = (const float*)d_in[1];
    const float* b_mlp   = (const float*)d_in[2];
    const float* emb_B   = (const float*)d_in[3];
    const float* rel0    = (const float*)d_in[4];
    const float* lrel0   = (const float*)d_in[5];
    const float* wloop0  = (const float*)d_in[6];
    const float* win0    = (const float*)d_in[7];
    const float* wout0   = (const float*)d_in[8];
    const float* bias0   = (const float*)d_in[9];
    const float* lng0    = (const float*)d_in[10];
    const float* lnb0    = (const float*)d_in[11];
    const float* rel1    = (const float*)d_in[12];
    const float* lrel1   = (const float*)d_in[13];
    const float* wloop1  = (const float*)d_in[14];
    const float* win1    = (const float*)d_in[15];
    const float* wout1   = (const float*)d_in[16];
    const float* bias1   = (const float*)d_in[17];
    const float* lng1    = (const float*)d_in[18];
    const float* lnb1    = (const float*)d_in[19];
    const int*   esrc    = (const int*)d_in[20];
    const int*   erel    = (const int*)d_in[21];
    const int*   edst    = (const int*)d_in[22];
    float* out = (float*)d_out;

    const int smem_mlp = CHUNK * DD * 4 + 64 * CHUNK * 8;   // 65536
    cudaFuncSetAttribute(k_mlp, cudaFuncAttributeMaxDynamicSharedMemorySize, smem_mlp);
    cudaFuncSetAttribute(k_fused_mma, cudaFuncAttributeMaxDynamicSharedMemorySize, SMF_MMA);

    const int nScanBlk = (NN + 511) / 512;   // 196
    const int nMmaBlk = (NN + 127) / 128;    // 782

    k_csr_zero<<<(NN + 255) / 256, 256>>>();
    k_hist<<<(NE + 255) / 256, 256>>>(esrc, edst);
    k_scan1<<<nScanBlk, 512>>>();
    k_scan2<<<1, 256>>>(nScanBlk);
    k_scan3<<<nScanBlk, 512>>>();

    k_mlp<<<(NA + 63) / 64, 256, smem_mlp>>>(x_typeA, W_mlp, b_mlp);
    k_fill<<<(NE + 255) / 256, 256>>>(esrc, erel, edst);
    k_copyB<<<2048, 256>>>(emb_B);
    // fragment order per layer: m0=Wout, m1=Win, m2=Wloop
    k_convB<<<(6 * 4096 + 255) / 256, 256>>>(wout0, win0, wloop0, wout1, win1, wloop1);

    k_gather<<<NN / 32, 256>>>(0, rel0);
    k_fused_mma<<<nMmaBlk, 256, SMF_MMA>>>(0, lrel0, bias0, lng0, lnb0, out);
    k_gather<<<NN / 32, 256>>>(1, rel1);
    k_fused_mma<<<nMmaBlk, 256, SMF_MMA>>>(1, lrel1, bias1, lng1, lnb1, out);
}